// round 4
// baseline (speedup 1.0000x reference)
#include <cuda_runtime.h>
#include <cuda_bf16.h>
#include <cstdint>

#define NODES 8192
#define N_ 2048
#define K_ 48
#define H_ 128
#define LDW 136
#define HV_ELEMS (NODES * H_)

__device__ __align__(16) float         g_v1[NODES * H_];
__device__ __align__(16) __nv_bfloat16 g_fb[NODES * 512];
__device__ __align__(16) __nv_bfloat16 g_hvb[NODES * H_];

static __device__ __forceinline__ unsigned su32(const void* p) {
    return (unsigned)__cvta_generic_to_shared(p);
}
static __device__ __forceinline__ void barx(int id) {
    asm volatile("bar.sync %0, %1;" :: "r"(id), "r"(256) : "memory");
}
static __device__ __forceinline__ float gelu_f(float x) {
    float u = 0.7978845608028654f * (x + 0.044715f * x * x * x), t;
    asm("tanh.approx.f32 %0, %1;" : "=f"(t) : "f"(u));
    return 0.5f * x * (1.0f + t);
}
static __device__ __forceinline__ void load_w(const float* g, __nv_bfloat16* s,
                                              int rows, int tid, int nthr) {
    int total4 = rows * 32;
    for (int i = tid; i < total4; i += nthr) {
        float4 w = ((const float4*)g)[i];
        int r = (i * 4) >> 7, c = (i * 4) & 127;
        *(__nv_bfloat162*)(s + r * LDW + c)     = __floats2bfloat162_rn(w.x, w.y);
        *(__nv_bfloat162*)(s + r * LDW + c + 2) = __floats2bfloat162_rn(w.z, w.w);
    }
}

// C[48x16] += A[48xKD] * W[KDx128] (16 cols at ncol0), one warp.
template <int KD>
static __device__ __forceinline__ void warp_gemm(const __nv_bfloat16* As, int lda,
                                                 const __nv_bfloat16* Ws,
                                                 int ncol0, float acc[3][2][4]) {
    const int lane = threadIdx.x & 31, lr = lane & 15, hi = lane >> 4;
    #pragma unroll
    for (int kt = 0; kt < KD; kt += 16) {
        unsigned a[3][4], b[2][2];
        #pragma unroll
        for (int mt = 0; mt < 3; ++mt) {
            unsigned ad = su32(As + (mt * 16 + lr) * lda + kt + hi * 8);
            asm volatile("ldmatrix.sync.aligned.m8n8.x4.shared.b16 {%0,%1,%2,%3},[%4];"
                         : "=r"(a[mt][0]), "=r"(a[mt][1]), "=r"(a[mt][2]), "=r"(a[mt][3])
                         : "r"(ad));
        }
        #pragma unroll
        for (int nt = 0; nt < 2; ++nt) {
            unsigned ad = su32(Ws + (kt + lr) * LDW + ncol0 + nt * 8);
            asm volatile("ldmatrix.sync.aligned.m8n8.x2.trans.shared.b16 {%0,%1},[%2];"
                         : "=r"(b[nt][0]), "=r"(b[nt][1]) : "r"(ad));
        }
        #pragma unroll
        for (int mt = 0; mt < 3; ++mt)
            #pragma unroll
            for (int nt = 0; nt < 2; ++nt)
                asm volatile("mma.sync.aligned.m16n8k16.row.col.f32.bf16.bf16.f32 "
                             "{%0,%1,%2,%3},{%4,%5,%6,%7},{%8,%9},{%0,%1,%2,%3};"
                             : "+f"(acc[mt][nt][0]), "+f"(acc[mt][nt][1]),
                               "+f"(acc[mt][nt][2]), "+f"(acc[mt][nt][3])
                             : "r"(a[mt][0]), "r"(a[mt][1]), "r"(a[mt][2]), "r"(a[mt][3]),
                               "r"(b[nt][0]), "r"(b[nt][1]));
    }
}
static __device__ __forceinline__ void zero_acc(float acc[3][2][4]) {
    #pragma unroll
    for (int m = 0; m < 3; ++m)
        #pragma unroll
        for (int n = 0; n < 2; ++n)
            #pragma unroll
            for (int i = 0; i < 4; ++i) acc[m][n][i] = 0.0f;
}
static __device__ __forceinline__ void epi_gelu_store(const float acc[3][2][4],
                                                      const float* bias,
                                                      __nv_bfloat16* dst, int lds,
                                                      int ncol0, int lane) {
    int gid = lane >> 2, tig = lane & 3;
    #pragma unroll
    for (int mt = 0; mt < 3; ++mt)
        #pragma unroll
        for (int nt = 0; nt < 2; ++nt) {
            int col = ncol0 + nt * 8 + 2 * tig;
            float b0 = bias[col], b1 = bias[col + 1];
            int r0 = mt * 16 + gid;
            *(__nv_bfloat162*)(dst + r0 * lds + col) = __floats2bfloat162_rn(
                gelu_f(acc[mt][nt][0] + b0), gelu_f(acc[mt][nt][1] + b1));
            *(__nv_bfloat162*)(dst + (r0 + 8) * lds + col) = __floats2bfloat162_rn(
                gelu_f(acc[mt][nt][2] + b0), gelu_f(acc[mt][nt][3] + b1));
        }
}
// per-node fold: bias1p[c] = bq[c] + sum_d hv[d] * Whv[d][c]  (64 threads, 2 cols each)
static __device__ __forceinline__ void fold_bias(int stid, const float* bq,
                                                 const __nv_bfloat16* Whv,
                                                 const float* hv_s, float* bias1p) {
    if (stid < 64) {
        int c2 = stid * 2;
        float a0 = bq[c2], a1 = bq[c2 + 1];
        #pragma unroll 4
        for (int d = 0; d < 128; ++d) {
            __nv_bfloat162 w = *(const __nv_bfloat162*)(Whv + d * LDW + c2);
            float h = hv_s[d];
            a0 += h * __low2float(w);
            a1 += h * __high2float(w);
        }
        bias1p[c2] = a0; bias1p[c2 + 1] = a1;
    }
}

// ============================ Kernel A ============================
// A = h_E only (h_V folded into bias). Weff rows: [W1(128:256) | W2 | W3]
#define SMEM_A_BYTES ((384 * LDW + 128 * LDW + 4 * 48 * 136) * 2 + (512 + 2 * 432) * 4)
__global__ void __launch_bounds__(512, 1)
kA(const float* __restrict__ hV, const float* __restrict__ hE,
   const float* __restrict__ matt,
   const float* __restrict__ W1, const float* __restrict__ b1,
   const float* __restrict__ W2, const float* __restrict__ b2,
   const float* __restrict__ W3, const float* __restrict__ b3,
   const float* __restrict__ g1, const float* __restrict__ bb1) {
    extern __shared__ char smem[];
    __nv_bfloat16* Wa  = (__nv_bfloat16*)smem;        // 384 x LDW
    __nv_bfloat16* Whv = Wa + 384 * LDW;              // 128 x LDW
    __nv_bfloat16* Ab0 = Whv + 128 * LDW;             // 2 x 48x136
    __nv_bfloat16* Mb0 = Ab0 + 2 * 48 * 136;          // 2 x 48x136
    float* fs = (float*)(Mb0 + 2 * 48 * 136);
    float* b2s = fs;        float* b3s = fs + 128;
    float* g1s = fs + 256;  float* bb1s = fs + 384;

    int tid = threadIdx.x, lane = tid & 31, warp = tid >> 5;
    int slot = warp >> 3, swarp = warp & 7, stid = tid & 255;
    int bid = 1 + slot;
    __nv_bfloat16* Abs = Ab0 + slot * 48 * 136;
    __nv_bfloat16* Mbs = Mb0 + slot * 48 * 136;
    float* sf = fs + 512 + slot * 432;
    float* hv_s = sf; float* dh_s = sf + 128; float* bias1p = sf + 256; float* mk_s = sf + 384;

    load_w(W1 + 128 * 128, Wa, 128, tid, 512);
    load_w(W2, Wa + 128 * LDW, 128, tid, 512);
    load_w(W3, Wa + 256 * LDW, 128, tid, 512);
    load_w(W1, Whv, 128, tid, 512);
    if (tid < 128) { b2s[tid] = b2[tid]; b3s[tid] = b3[tid];
                     g1s[tid] = g1[tid]; bb1s[tid] = bb1[tid]; }
    __syncthreads();

    for (int ni = 0; ni < 8; ++ni) {
        int node = blockIdx.x * 16 + slot * 8 + ni;
        barx(bid);
        if (stid < 128) hv_s[stid] = hV[node * H_ + stid];
        if (stid < 48)  mk_s[stid] = matt[node * K_ + stid];
        if (stid >= 128)
            for (int i = stid - 128; i < 48 * 32; i += 128) {
                int k = i >> 5, c = (i & 31) * 4;
                float4 e = *(const float4*)(hE + ((size_t)node * K_ + k) * H_ + c);
                *(__nv_bfloat162*)(Abs + k * 136 + c)     = __floats2bfloat162_rn(e.x, e.y);
                *(__nv_bfloat162*)(Abs + k * 136 + c + 2) = __floats2bfloat162_rn(e.z, e.w);
            }
        barx(bid);
        fold_bias(stid, b1, Whv, hv_s, bias1p);
        barx(bid);
        float acc[3][2][4];
        zero_acc(acc);
        warp_gemm<128>(Abs, 136, Wa, swarp * 16, acc);
        epi_gelu_store(acc, bias1p, Mbs, 136, swarp * 16, lane);
        barx(bid);
        zero_acc(acc);
        warp_gemm<128>(Mbs, 136, Wa + 128 * LDW, swarp * 16, acc);
        epi_gelu_store(acc, b2s, Abs, 136, swarp * 16, lane);
        barx(bid);
        zero_acc(acc);
        warp_gemm<128>(Abs, 136, Wa + 256 * LDW, swarp * 16, acc);
        {   // masked sum over 48 rows
            int gid = lane >> 2, tig = lane & 3;
            float s[2][2] = {{0.f, 0.f}, {0.f, 0.f}};
            #pragma unroll
            for (int mt = 0; mt < 3; ++mt)
                #pragma unroll
                for (int nt = 0; nt < 2; ++nt) {
                    int col = swarp * 16 + nt * 8 + 2 * tig;
                    int r0 = mt * 16 + gid;
                    float m0 = mk_s[r0], m1 = mk_s[r0 + 8];
                    s[nt][0] += (acc[mt][nt][0] + b3s[col])     * m0
                              + (acc[mt][nt][2] + b3s[col])     * m1;
                    s[nt][1] += (acc[mt][nt][1] + b3s[col + 1]) * m0
                              + (acc[mt][nt][3] + b3s[col + 1]) * m1;
                }
            #pragma unroll
            for (int off = 4; off < 32; off <<= 1) {
                s[0][0] += __shfl_xor_sync(~0u, s[0][0], off);
                s[0][1] += __shfl_xor_sync(~0u, s[0][1], off);
                s[1][0] += __shfl_xor_sync(~0u, s[1][0], off);
                s[1][1] += __shfl_xor_sync(~0u, s[1][1], off);
            }
            if (lane < 4) {
                dh_s[swarp * 16 + 2 * lane]         = s[0][0];
                dh_s[swarp * 16 + 2 * lane + 1]     = s[0][1];
                dh_s[swarp * 16 + 8 + 2 * lane]     = s[1][0];
                dh_s[swarp * 16 + 8 + 2 * lane + 1] = s[1][1];
            }
        }
        barx(bid);
        if (swarp == 0) {   // LN1
            float x[4];
            #pragma unroll
            for (int q = 0; q < 4; ++q)
                x[q] = hv_s[lane * 4 + q] + dh_s[lane * 4 + q] * (1.0f / 30.0f);
            float sm = x[0] + x[1] + x[2] + x[3];
            #pragma unroll
            for (int off = 16; off >= 1; off >>= 1) sm += __shfl_xor_sync(~0u, sm, off);
            float mu = sm * (1.0f / 128.0f), vs = 0.f;
            #pragma unroll
            for (int q = 0; q < 4; ++q) { float d = x[q] - mu; vs += d * d; }
            #pragma unroll
            for (int off = 16; off >= 1; off >>= 1) vs += __shfl_xor_sync(~0u, vs, off);
            float inv = rsqrtf(vs * (1.0f / 128.0f) + 1e-5f);
            #pragma unroll
            for (int q = 0; q < 4; ++q) {
                int c = lane * 4 + q;
                g_v1[node * H_ + c] = (x[q] - mu) * inv * g1s[c] + bb1s[c];
            }
        }
    }
}

// ============================ FFN kernels ============================
#define SMEM_F1_BYTES (128 * 512 * 2 + 768 * 4)
__global__ void __launch_bounds__(512, 1)
kF1(const float* __restrict__ Win, const float* __restrict__ bin) {
    extern __shared__ char smem[];
    __nv_bfloat16* Ws = (__nv_bfloat16*)smem;
    float* bin_s = (float*)(Ws + 128 * 512);
    float* v_s = bin_s + 512;
    int tid = threadIdx.x;
    for (int i = tid; i < 16384; i += 512) {
        float4 w = ((const float4*)Win)[i];
        *(__nv_bfloat162*)(Ws + i * 4)     = __floats2bfloat162_rn(w.x, w.y);
        *(__nv_bfloat162*)(Ws + i * 4 + 2) = __floats2bfloat162_rn(w.z, w.w);
    }
    bin_s[tid] = bin[tid];
    int rowbase = blockIdx.x * 32;
    for (int p = 0; p < 16; ++p) {
        __syncthreads();
        int r0 = rowbase + 2 * p;
        if (tid < 256) v_s[tid] = g_v1[(size_t)(r0 + (tid >> 7)) * H_ + (tid & 127)];
        __syncthreads();
        float a0 = bin_s[tid], a1 = a0;
        #pragma unroll 8
        for (int d = 0; d < 128; ++d) {
            float w = __bfloat162float(Ws[d * 512 + tid]);
            a0 += v_s[d] * w;
            a1 += v_s[128 + d] * w;
        }
        g_fb[(size_t)r0 * 512 + tid]       = __float2bfloat16(gelu_f(a0));
        g_fb[(size_t)(r0 + 1) * 512 + tid] = __float2bfloat16(gelu_f(a1));
    }
}

#define SMEM_F2_BYTES (512 * 128 * 2 + (1024 + 256 + 384 + 16) * 4)
__global__ void __launch_bounds__(256, 1)
kF2(const float* __restrict__ Wout, const float* __restrict__ bout,
    const float* __restrict__ g2, const float* __restrict__ bb2,
    const float* __restrict__ maskV, float* __restrict__ outV) {
    extern __shared__ char smem[];
    __nv_bfloat16* Ws = (__nv_bfloat16*)smem;
    float* f_s = (float*)(Ws + 512 * 128);
    float* v_s = f_s + 1024;
    float* bo_s = v_s + 256; float* g2s = bo_s + 128; float* b2s = g2s + 128;
    float* red = b2s + 128;  float* red2 = red + 8;
    int tid = threadIdx.x, lane = tid & 31;
    for (int i = tid; i < 16384; i += 256) {
        float4 w = ((const float4*)Wout)[i];
        *(__nv_bfloat162*)(Ws + i * 4)     = __floats2bfloat162_rn(w.x, w.y);
        *(__nv_bfloat162*)(Ws + i * 4 + 2) = __floats2bfloat162_rn(w.z, w.w);
    }
    if (tid < 128) { bo_s[tid] = bout[tid]; g2s[tid] = g2[tid]; b2s[tid] = bb2[tid]; }
    int rowbase = blockIdx.x * 32;
    int row = tid >> 7, c = tid & 127, wig = (tid >> 5) & 3;
    for (int p = 0; p < 16; ++p) {
        __syncthreads();
        int r0 = rowbase + 2 * p;
        #pragma unroll
        for (int i = tid; i < 512; i += 256) {
            int rr = i >> 8, cc = i & 255;
            __nv_bfloat162 v = ((const __nv_bfloat162*)(g_fb + (size_t)(r0 + rr) * 512))[cc];
            f_s[rr * 512 + 2 * cc]     = __low2float(v);
            f_s[rr * 512 + 2 * cc + 1] = __high2float(v);
        }
        v_s[row * 128 + c] = g_v1[(size_t)(r0 + row) * H_ + c];
        __syncthreads();
        float acc = bo_s[c];
        #pragma unroll 8
        for (int d = 0; d < 512; ++d)
            acc += f_s[row * 512 + d] * __bfloat162float(Ws[d * 128 + c]);
        float x = v_s[row * 128 + c] + acc;
        float sm = x;
        #pragma unroll
        for (int off = 16; off >= 1; off >>= 1) sm += __shfl_xor_sync(~0u, sm, off);
        if (lane == 0) red[row * 4 + wig] = sm;
        __syncthreads();
        float mu = (red[row * 4] + red[row * 4 + 1] + red[row * 4 + 2] + red[row * 4 + 3])
                   * (1.0f / 128.0f);
        float dv = x - mu, sq = dv * dv;
        #pragma unroll
        for (int off = 16; off >= 1; off >>= 1) sq += __shfl_xor_sync(~0u, sq, off);
        if (lane == 0) red2[row * 4 + wig] = sq;
        __syncthreads();
        float var = (red2[row * 4] + red2[row * 4 + 1] + red2[row * 4 + 2] + red2[row * 4 + 3])
                    * (1.0f / 128.0f);
        int gr = r0 + row;
        float y = (dv * rsqrtf(var + 1e-5f) * g2s[c] + b2s[c]) * maskV[gr];
        outV[(size_t)gr * H_ + c] = y;
        g_hvb[(size_t)gr * H_ + c] = __float2bfloat16(y);
    }
}

// ============================ Kernel C ============================
// A = [h_E | nbr] (K=256, h_V folded). Wc rows: [W11(128:384) | W12 | W13]
#define SMEM_C_BYTES ((512 * LDW + 128 * LDW + 2 * 48 * 264) * 2 + 1024 * 4 + 2 * 48 * 4)
__global__ void __launch_bounds__(512, 1)
kC(const float* __restrict__ hE, const int* __restrict__ Eidx,
   const float* __restrict__ hVfin,
   const float* __restrict__ W11, const float* __restrict__ b11,
   const float* __restrict__ W12, const float* __restrict__ b12,
   const float* __restrict__ W13, const float* __restrict__ b13,
   const float* __restrict__ g3, const float* __restrict__ bb3,
   float* __restrict__ outE) {
    extern __shared__ char smem[];
    __nv_bfloat16* Wc   = (__nv_bfloat16*)smem;       // 512 x LDW
    __nv_bfloat16* Whvc = Wc + 512 * LDW;             // 128 x LDW
    __nv_bfloat16* Ab0  = Whvc + 128 * LDW;           // 2 x 48x264
    float* fs = (float*)(Ab0 + 2 * 48 * 264);
    float* b2s = fs;        float* b3s = fs + 128;
    float* g3s = fs + 256;  float* bb3s = fs + 384;
    int*  idx0 = (int*)(fs + 1024);

    int tid = threadIdx.x, lane = tid & 31, warp = tid >> 5;
    int slot = warp >> 3, swarp = warp & 7, stid = tid & 255;
    int bid = 1 + slot;
    __nv_bfloat16* Abs = Ab0 + slot * 48 * 264;
    float* sf = fs + 512 + slot * 256;
    float* hv_s = sf; float* bias1p = sf + 128;
    int* idx_s = idx0 + slot * 48;

    load_w(W11 + 128 * 128, Wc, 256, tid, 512);
    load_w(W12, Wc + 256 * LDW, 128, tid, 512);
    load_w(W13, Wc + 384 * LDW, 128, tid, 512);
    load_w(W11, Whvc, 128, tid, 512);
    if (tid < 128) { b2s[tid] = b12[tid]; b3s[tid] = b13[tid];
                     g3s[tid] = g3[tid];  bb3s[tid] = bb3[tid]; }
    __syncthreads();

    for (int ni = 0; ni < 8; ++ni) {
        int node = blockIdx.x * 16 + slot * 8 + ni;
        int bbase = (node >> 11) << 11;
        barx(bid);
        if (stid < 48)  idx_s[stid] = Eidx[node * K_ + stid];
        if (stid < 128) hv_s[stid] = hVfin[node * H_ + stid];
        if (stid >= 128)
            for (int i = stid - 128; i < 48 * 32; i += 128) {
                int k = i >> 5, c = (i & 31) * 4;
                float4 e = *(const float4*)(hE + ((size_t)node * K_ + k) * H_ + c);
                *(__nv_bfloat162*)(Abs + k * 264 + c)     = __floats2bfloat162_rn(e.x, e.y);
                *(__nv_bfloat162*)(Abs + k * 264 + c + 2) = __floats2bfloat162_rn(e.z, e.w);
            }
        barx(bid);
        fold_bias(stid, b11, Whvc, hv_s, bias1p);
        if (stid >= 128)
            for (int i = stid - 128; i < 48 * 64; i += 128) {
                int k = i >> 6, c = (i & 63) * 2;
                int nb = bbase + idx_s[k];
                *(__nv_bfloat162*)(Abs + k * 264 + 128 + c) =
                    *(const __nv_bfloat162*)(g_hvb + (size_t)nb * H_ + c);
            }
        barx(bid);
        float acc[3][2][4];
        zero_acc(acc);
        warp_gemm<256>(Abs, 264, Wc, swarp * 16, acc);   // layer 1 (reads cols 0..255)
        barx(bid);
        epi_gelu_store(acc, bias1p, Abs, 264, swarp * 16, lane);   // M1 -> cols 0..127
        barx(bid);
        zero_acc(acc);
        warp_gemm<128>(Abs, 264, Wc + 256 * LDW, swarp * 16, acc); // layer 2 reads M1
        epi_gelu_store(acc, b2s, Abs + 136, 264, swarp * 16, lane); // M2 -> cols 136..263
        barx(bid);
        zero_acc(acc);
        warp_gemm<128>(Abs + 136, 264, Wc + 384 * LDW, swarp * 16, acc); // layer 3
        barx(bid);
        {   // X (fp32 msg) overlays Abs rows (bytes 0..511 of each 528B row)
            int gid = lane >> 2, tig = lane & 3;
            #pragma unroll
            for (int mt = 0; mt < 3; ++mt)
                #pragma unroll
                for (int nt = 0; nt < 2; ++nt) {
                    int col = swarp * 16 + nt * 8 + 2 * tig;
                    int r0 = mt * 16 + gid;
                    float* X0 = (float*)(Abs + (size_t)r0 * 264);
                    float* X1 = (float*)(Abs + (size_t)(r0 + 8) * 264);
                    X0[col]     = acc[mt][nt][0] + b3s[col];
                    X0[col + 1] = acc[mt][nt][1] + b3s[col + 1];
                    X1[col]     = acc[mt][nt][2] + b3s[col];
                    X1[col + 1] = acc[mt][nt][3] + b3s[col + 1];
                }
        }
        barx(bid);
        for (int rr = 0; rr < 6; ++rr) {   // LN3: warp w -> rows w*6..w*6+5
            int r = swarp * 6 + rr;
            const float* ep = hE + ((size_t)node * K_ + r) * H_;
            const float* Xr = (const float*)(Abs + (size_t)r * 264);
            float x[4];
            #pragma unroll
            for (int q = 0; q < 4; ++q)
                x[q] = ep[lane * 4 + q] + Xr[lane * 4 + q];
            float sm = x[0] + x[1] + x[2] + x[3];
            #pragma unroll
            for (int off = 16; off >= 1; off >>= 1) sm += __shfl_xor_sync(~0u, sm, off);
            float mu = sm * (1.0f / 128.0f), vs = 0.f;
            #pragma unroll
            for (int q = 0; q < 4; ++q) { float d = x[q] - mu; vs += d * d; }
            #pragma unroll
            for (int off = 16; off >= 1; off >>= 1) vs += __shfl_xor_sync(~0u, vs, off);
            float inv = rsqrtf(vs * (1.0f / 128.0f) + 1e-5f);
            float* op = outE + ((size_t)node * K_ + r) * H_;
            #pragma unroll
            for (int q = 0; q < 4; ++q) {
                int c = lane * 4 + q;
                op[c] = (x[q] - mu) * inv * g3s[c] + bb3s[c];
            }
        }
    }
}

// ============================ launch ============================
extern "C" void kernel_launch(void* const* d_in, const int* in_sizes, int n_in,
                              void* d_out, int out_size) {
    const float* hV   = (const float*)d_in[0];
    const float* hE   = (const float*)d_in[1];
    const float* mV   = (const float*)d_in[2];
    const int*   Eidx = (const int*)d_in[3];
    const float* matt = (const float*)d_in[4];
    const float* W1 = (const float*)d_in[5],  *b1 = (const float*)d_in[6];
    const float* W2 = (const float*)d_in[7],  *b2 = (const float*)d_in[8];
    const float* W3 = (const float*)d_in[9],  *b3 = (const float*)d_in[10];
    const float* W11 = (const float*)d_in[11], *b11 = (const float*)d_in[12];
    const float* W12 = (const float*)d_in[13], *b12 = (const float*)d_in[14];
    const float* W13 = (const float*)d_in[15], *b13 = (const float*)d_in[16];
    const float* Win = (const float*)d_in[17], *bin = (const float*)d_in[18];
    const float* Wout = (const float*)d_in[19], *bout = (const float*)d_in[20];
    const float* g1 = (const float*)d_in[21], *bb1 = (const float*)d_in[22];
    const float* g2 = (const float*)d_in[23], *bb2 = (const float*)d_in[24];
    const float* g3 = (const float*)d_in[25], *bb3 = (const float*)d_in[26];
    float* outV = (float*)d_out;
    float* outE = (float*)d_out + HV_ELEMS;

    static bool configured = false;
    if (!configured) {
        cudaFuncSetAttribute(kA,  cudaFuncAttributeMaxDynamicSharedMemorySize, SMEM_A_BYTES);
        cudaFuncSetAttribute(kF1, cudaFuncAttributeMaxDynamicSharedMemorySize, SMEM_F1_BYTES);
        cudaFuncSetAttribute(kF2, cudaFuncAttributeMaxDynamicSharedMemorySize, SMEM_F2_BYTES);
        cudaFuncSetAttribute(kC,  cudaFuncAttributeMaxDynamicSharedMemorySize, SMEM_C_BYTES);
        configured = true;
    }
    kA<<<NODES / 16, 512, SMEM_A_BYTES>>>(hV, hE, matt, W1, b1, W2, b2, W3, b3, g1, bb1);
    kF1<<<NODES / 32, 512, SMEM_F1_BYTES>>>(Win, bin);
    kF2<<<NODES / 32, 256, SMEM_F2_BYTES>>>(Wout, bout, g2, bb2, mV, outV);
    kC<<<NODES / 16, 512, SMEM_C_BYTES>>>(hE, Eidx, outV, W11, b11, W12, b12, W13, b13,
                                          g3, bb3, outE);
}

// round 7
// speedup vs baseline: 1.1058x; 1.1058x over previous
#include <cuda_runtime.h>
#include <cuda_bf16.h>
#include <cstdint>

#define NODES 8192
#define H_ 128
#define K_ 48
#define EDGES (NODES * K_)
#define TILES (EDGES / 128)
#define HV_ELEMS (NODES * H_)
#define LDW 136

__device__ __align__(16) float         g_v1[NODES * H_];
__device__ __align__(16) __nv_bfloat16 g_fb[NODES * 512];
__device__ __align__(16) __nv_bfloat16 g_hvb[NODES * H_];
__device__ __align__(16) float         g_dh[NODES * H_];
__device__ __align__(16) float         g_biasA[NODES * H_];
__device__ __align__(16) float         g_biasC[NODES * H_];

static __device__ __forceinline__ unsigned su32(const void* p) {
    return (unsigned)__cvta_generic_to_shared(p);
}
static __device__ __forceinline__ float gelu_f(float x) {
    float u = 0.7978845608028654f * (x + 0.044715f * x * x * x), t;
    asm("tanh.approx.f32 %0, %1;" : "=f"(t) : "f"(u));
    return 0.5f * x * (1.0f + t);
}
static __device__ __forceinline__ void load_w(const float* g, __nv_bfloat16* s,
                                              int rows, int tid, int nthr) {
    int total4 = rows * 32;
    for (int i = tid; i < total4; i += nthr) {
        float4 w = ((const float4*)g)[i];
        int r = (i * 4) >> 7, c = (i * 4) & 127;
        *(__nv_bfloat162*)(s + r * LDW + c)     = __floats2bfloat162_rn(w.x, w.y);
        *(__nv_bfloat162*)(s + r * LDW + c + 2) = __floats2bfloat162_rn(w.z, w.w);
    }
}

#define MMA4(ac, a, b0, b1) \
    asm volatile("mma.sync.aligned.m16n8k16.row.col.f32.bf16.bf16.f32 " \
                 "{%0,%1,%2,%3},{%4,%5,%6,%7},{%8,%9},{%0,%1,%2,%3};" \
                 : "+f"((ac)[0]), "+f"((ac)[1]), "+f"((ac)[2]), "+f"((ac)[3]) \
                 : "r"((a)[0]), "r"((a)[1]), "r"((a)[2]), "r"((a)[3]), \
                   "r"(b0), "r"(b1))

static __device__ __forceinline__ void zero16(float acc[16][4]) {
    #pragma unroll
    for (int i = 0; i < 16; ++i)
        #pragma unroll
        for (int j = 0; j < 4; ++j) acc[i][j] = 0.0f;
}

// C[16x128] += A[16xNK] * W[NKx128]; A row-major LDW=136 at aAddr, W at wAddr.
template <int NK>
static __device__ __forceinline__ void gemm16(uint32_t aAddr, uint32_t wAddr,
                                              float acc[16][4]) {
    #pragma unroll
    for (int kt = 0; kt < NK; kt += 16) {
        uint32_t a[4];
        asm volatile("ldmatrix.sync.aligned.m8n8.x4.shared.b16 {%0,%1,%2,%3},[%4];"
                     : "=r"(a[0]), "=r"(a[1]), "=r"(a[2]), "=r"(a[3])
                     : "r"(aAddr + kt * 2));
        #pragma unroll
        for (int nb = 0; nb < 8; ++nb) {
            uint32_t b[4];
            asm volatile("ldmatrix.sync.aligned.m8n8.x4.trans.shared.b16 {%0,%1,%2,%3},[%4];"
                         : "=r"(b[0]), "=r"(b[1]), "=r"(b[2]), "=r"(b[3])
                         : "r"(wAddr + kt * 272 + nb * 32));
            MMA4(acc[2 * nb],     a, b[0], b[1]);
            MMA4(acc[2 * nb + 1], a, b[2], b[3]);
        }
    }
}

static __device__ __forceinline__ void epi_gelu_w(const float acc[16][4],
        const float* br0, const float* br1, __nv_bfloat16* dst, int lane) {
    int gid = lane >> 2, tg = lane & 3;
    #pragma unroll
    for (int nt = 0; nt < 16; ++nt) {
        int col = nt * 8 + tg * 2;
        *(__nv_bfloat162*)(dst + gid * LDW + col) = __floats2bfloat162_rn(
            gelu_f(acc[nt][0] + br0[col]), gelu_f(acc[nt][1] + br0[col + 1]));
        *(__nv_bfloat162*)(dst + (gid + 8) * LDW + col) = __floats2bfloat162_rn(
            gelu_f(acc[nt][2] + br1[col]), gelu_f(acc[nt][3] + br1[col + 1]));
    }
}

// ================= kFold: out[node] = b + x[node] @ W[0:128] ; opt zero g_dh =========
#define KFOLD_SMEM ((16384 + 2048) * 4)
__global__ void __launch_bounds__(256)
kFold(const float* __restrict__ x, const float* __restrict__ W,
      const float* __restrict__ b, float* __restrict__ out, int zdh) {
    extern __shared__ float sfold[];
    float* Ws = sfold;          // 16384
    float* xs = sfold + 16384;  // 2048
    int tid = threadIdx.x, n0 = blockIdx.x * 16;
    for (int i = tid; i < 16384; i += 256) Ws[i] = W[i];
    for (int i = tid; i < 2048; i += 256) xs[i] = x[(size_t)n0 * 128 + i];
    if (zdh) for (int i = tid; i < 2048; i += 256) g_dh[(size_t)n0 * 128 + i] = 0.0f;
    __syncthreads();
    int c = tid & 127, h = tid >> 7;
    for (int ni = 0; ni < 8; ++ni) {
        int nl = h * 8 + ni;
        float acc = b[c];
        #pragma unroll 8
        for (int d = 0; d < 128; ++d) acc += xs[nl * 128 + d] * Ws[d * 128 + c];
        out[(size_t)(n0 + nl) * 128 + c] = acc;
    }
}

// ================= kEdge: per-warp M=16 x N=128, 3 layers, no inter-warp deps ========
// smem: W1s 256x136 | W2s 128x136 | W3s 128x136 | biases 512f | 8 x (inA 16x136 + act 16x136)
#define KE_SMEM (139264 + 2048 + 8 * 8704)
__global__ void __launch_bounds__(256, 1)
kEdge(int mode, const float* __restrict__ hE,
      const float* __restrict__ Wl1, const float* __restrict__ Wl2,
      const float* __restrict__ Wl3, int K1,
      const float* __restrict__ b2, const float* __restrict__ b3,
      const float* __restrict__ bias1, const float* __restrict__ matt,
      const int* __restrict__ Eidx, const float* __restrict__ g3,
      const float* __restrict__ bb3, float* __restrict__ outE) {
    extern __shared__ char sm[];
    __nv_bfloat16* W1s = (__nv_bfloat16*)sm;
    __nv_bfloat16* W2s = (__nv_bfloat16*)(sm + 69632);
    __nv_bfloat16* W3s = (__nv_bfloat16*)(sm + 104448);
    float* bs = (float*)(sm + 139264);
    char* PB = sm + 141312;
    int tid = threadIdx.x, lane = tid & 31, warp = tid >> 5;
    char* mybuf = PB + warp * 8704;
    __nv_bfloat16* inA = (__nv_bfloat16*)mybuf;
    __nv_bfloat16* act = (__nv_bfloat16*)(mybuf + 4352);
    float* stage = (float*)mybuf;     // 16 x 132 fp32 overlay (after gemm3)

    load_w(Wl1, W1s, K1, tid, 256);
    load_w(Wl2, W2s, 128, tid, 256);
    load_w(Wl3, W3s, 128, tid, 256);
    if (tid < 128) {
        bs[tid] = b2[tid]; bs[128 + tid] = b3[tid];
        if (mode) { bs[256 + tid] = g3[tid]; bs[384 + tid] = bb3[tid]; }
    }
    __syncthreads();
    float* b2s = bs; float* b3s = bs + 128; float* g3s = bs + 256; float* bb3s = bs + 384;

    uint32_t loff = (uint32_t)(((lane & 15) * LDW + ((lane >> 4) * 8)) * 2);
    uint32_t aAddr  = su32(inA) + loff;
    uint32_t cAddr  = su32(act) + loff;
    uint32_t w1Addr = su32(W1s) + loff;
    uint32_t w2Addr = su32(W2s) + loff;
    uint32_t w3Addr = su32(W3s) + loff;
    int gid = lane >> 2, tg = lane & 3;

    for (int tile = blockIdx.x; tile < TILES; tile += gridDim.x) {
        int rowbase = tile * 128 + warp * 16;
        float acc[16][4];
        // stage hE rows -> inA (bf16)
        for (int i = lane; i < 16 * 32; i += 32) {
            int r = i >> 5, c4 = (i & 31) * 4;
            float4 v = *(const float4*)(hE + (size_t)(rowbase + r) * 128 + c4);
            *(__nv_bfloat162*)(inA + r * LDW + c4)     = __floats2bfloat162_rn(v.x, v.y);
            *(__nv_bfloat162*)(inA + r * LDW + c4 + 2) = __floats2bfloat162_rn(v.z, v.w);
        }
        __syncwarp();
        zero16(acc);
        gemm16<128>(aAddr, w1Addr, acc);          // K chunk: hE part
        if (mode) {                                // K chunk 2: gathered neighbor h_V
            __syncwarp();
            for (int i = lane; i < 16 * 64; i += 32) {
                int r = i >> 6, c2 = (i & 63) * 2, e = rowbase + r;
                int nb = (e / 98304) * 2048 + Eidx[e];
                *(uint32_t*)(inA + r * LDW + c2) =
                    *(const uint32_t*)(g_hvb + (size_t)nb * 128 + c2);
            }
            __syncwarp();
            gemm16<128>(aAddr, w1Addr + 128 * 272, acc);
        }
        {   // epi1 (per-node folded bias) -> act
            const float* brA0 = bias1 + (size_t)((rowbase + gid) / 48) * 128;
            const float* brA1 = bias1 + (size_t)((rowbase + gid + 8) / 48) * 128;
            epi_gelu_w(acc, brA0, brA1, act, lane);
        }
        __syncwarp();
        zero16(acc);
        gemm16<128>(cAddr, w2Addr, acc);          // layer 2 reads act
        __syncwarp();
        epi_gelu_w(acc, b2s, b2s, inA, lane);     // epi2 -> inA
        __syncwarp();
        zero16(acc);
        gemm16<128>(aAddr, w3Addr, acc);          // layer 3 reads inA
        __syncwarp();                              // stage overlays inA+act below

        if (mode == 0) {
            float m0 = matt[rowbase + gid], m1 = matt[rowbase + gid + 8];
            #pragma unroll
            for (int nt = 0; nt < 16; ++nt) {
                int col = nt * 8 + tg * 2, sc = col + 2 * (nt >> 3);
                float2 v0 = { (acc[nt][0] + b3s[col]) * m0, (acc[nt][1] + b3s[col + 1]) * m0 };
                float2 v1 = { (acc[nt][2] + b3s[col]) * m1, (acc[nt][3] + b3s[col + 1]) * m1 };
                *(float2*)(stage + gid * 132 + sc)       = v0;
                *(float2*)(stage + (gid + 8) * 132 + sc) = v1;
            }
            __syncthreads();
            if (tid < 128) {                      // segmented column sums -> g_dh
                int c = tid, sc = c + 2 * (c >> 6);
                int t0 = tile * 128, node = t0 / 48, kk = t0 % 48;
                float s = 0.0f;
                #pragma unroll 4
                for (int r = 0; r < 128; ++r) {
                    if (kk == 48) { atomicAdd(&g_dh[(size_t)node * 128 + c], s); s = 0.0f; node++; kk = 0; }
                    s += *((float*)(PB + (r >> 4) * 8704) + (r & 15) * 132 + sc);
                    kk++;
                }
                atomicAdd(&g_dh[(size_t)node * 128 + c], s);
            }
            __syncthreads();
        } else {
            #pragma unroll
            for (int nt = 0; nt < 16; ++nt) {     // msg fp32 -> stage
                int col = nt * 8 + tg * 2, sc = col + 2 * (nt >> 3);
                float2 v0 = { acc[nt][0] + b3s[col], acc[nt][1] + b3s[col + 1] };
                float2 v1 = { acc[nt][2] + b3s[col], acc[nt][3] + b3s[col + 1] };
                *(float2*)(stage + gid * 132 + sc)       = v0;
                *(float2*)(stage + (gid + 8) * 132 + sc) = v1;
            }
            __syncwarp();
            {   // LN3: 2 lanes per row, warp-local
                int r = lane >> 1, half = lane & 1, e = rowbase + r;
                float* srow = stage + r * 132;
                float sum = 0.0f, sq = 0.0f;
                #pragma unroll 4
                for (int q = 0; q < 16; ++q) {
                    float4 v = *(const float4*)(hE + (size_t)e * 128 + half * 64 + q * 4);
                    #pragma unroll
                    for (int u = 0; u < 4; ++u) {
                        int c = half * 64 + q * 4 + u, sc = c + 2 * (c >> 6);
                        float xv = (&v.x)[u] + srow[sc];
                        srow[sc] = xv;
                        sum += xv; sq += xv * xv;
                    }
                }
                sum += __shfl_xor_sync(~0u, sum, 1);
                sq  += __shfl_xor_sync(~0u, sq, 1);
                float mu = sum * (1.0f / 128.0f);
                float inv = rsqrtf(sq * (1.0f / 128.0f) - mu * mu + 1e-5f);
                #pragma unroll 4
                for (int q = 0; q < 16; ++q) {
                    float4 o;
                    #pragma unroll
                    for (int u = 0; u < 4; ++u) {
                        int c = half * 64 + q * 4 + u, sc = c + 2 * (c >> 6);
                        (&o.x)[u] = (srow[sc] - mu) * inv * g3s[c] + bb3s[c];
                    }
                    *(float4*)(outE + (size_t)e * 128 + half * 64 + q * 4) = o;
                }
            }
            __syncwarp();
        }
    }
}

// ================= kLN1 =================
__global__ void __launch_bounds__(128)
kLN1(const float* __restrict__ hV, const float* __restrict__ g1, const float* __restrict__ b1) {
    __shared__ float red[8];
    int n = blockIdx.x, c = threadIdx.x, lane = c & 31, w = c >> 5;
    float x = hV[(size_t)n * 128 + c] + g_dh[(size_t)n * 128 + c] * (1.0f / 30.0f);
    float s = x;
    for (int o = 16; o >= 1; o >>= 1) s += __shfl_xor_sync(~0u, s, o);
    if (!lane) red[w] = s;
    __syncthreads();
    float mu = (red[0] + red[1] + red[2] + red[3]) * (1.0f / 128.0f);
    float d = x - mu, q = d * d;
    for (int o = 16; o >= 1; o >>= 1) q += __shfl_xor_sync(~0u, q, o);
    if (!lane) red[4 + w] = q;
    __syncthreads();
    float var = (red[4] + red[5] + red[6] + red[7]) * (1.0f / 128.0f);
    g_v1[(size_t)n * 128 + c] = d * rsqrtf(var + 1e-5f) * g1[c] + b1[c];
}

// ================= FFN =================
#define SF1 (128 * 512 * 2 + 768 * 4)
__global__ void __launch_bounds__(512, 1)
kF1(const float* __restrict__ Win, const float* __restrict__ bin) {
    extern __shared__ char smem[];
    __nv_bfloat16* Ws = (__nv_bfloat16*)smem;
    float* bs = (float*)(Ws + 128 * 512); float* vs = bs + 512;
    int tid = threadIdx.x;
    for (int i = tid; i < 16384; i += 512) {
        float4 w = ((const float4*)Win)[i];
        *(__nv_bfloat162*)(Ws + i * 4) = __floats2bfloat162_rn(w.x, w.y);
        *(__nv_bfloat162*)(Ws + i * 4 + 2) = __floats2bfloat162_rn(w.z, w.w);
    }
    bs[tid] = bin[tid];
    int rb = blockIdx.x * 32;
    for (int p = 0; p < 16; ++p) {
        __syncthreads();
        int r0 = rb + 2 * p;
        if (tid < 256) vs[tid] = g_v1[(size_t)(r0 + (tid >> 7)) * 128 + (tid & 127)];
        __syncthreads();
        float a0 = bs[tid], a1 = a0;
        #pragma unroll 8
        for (int d = 0; d < 128; ++d) {
            float w = __bfloat162float(Ws[d * 512 + tid]);
            a0 += vs[d] * w; a1 += vs[128 + d] * w;
        }
        g_fb[(size_t)r0 * 512 + tid] = __float2bfloat16(gelu_f(a0));
        g_fb[(size_t)(r0 + 1) * 512 + tid] = __float2bfloat16(gelu_f(a1));
    }
}

#define SF2 (512 * 128 * 2 + (1024 + 256 + 384 + 16) * 4)
__global__ void __launch_bounds__(256, 1)
kF2(const float* __restrict__ Wout, const float* __restrict__ bout,
    const float* __restrict__ g2, const float* __restrict__ bb2,
    const float* __restrict__ maskV, float* __restrict__ outV) {
    extern __shared__ char smem[];
    __nv_bfloat16* Ws = (__nv_bfloat16*)smem;
    float* fs = (float*)(Ws + 512 * 128); float* vs = fs + 1024;
    float* bo = vs + 256; float* g2s = bo + 128; float* b2s = g2s + 128;
    float* red = b2s + 128; float* red2 = red + 8;
    int tid = threadIdx.x, lane = tid & 31;
    for (int i = tid; i < 16384; i += 256) {
        float4 w = ((const float4*)Wout)[i];
        *(__nv_bfloat162*)(Ws + i * 4) = __floats2bfloat162_rn(w.x, w.y);
        *(__nv_bfloat162*)(Ws + i * 4 + 2) = __floats2bfloat162_rn(w.z, w.w);
    }
    if (tid < 128) { bo[tid] = bout[tid]; g2s[tid] = g2[tid]; b2s[tid] = bb2[tid]; }
    int rb = blockIdx.x * 32, row = tid >> 7, c = tid & 127, wig = (tid >> 5) & 3;
    for (int p = 0; p < 16; ++p) {
        __syncthreads();
        int r0 = rb + 2 * p;
        for (int i = tid; i < 512; i += 256) {
            int rr = i >> 8, cc = i & 255;
            __nv_bfloat162 v = ((const __nv_bfloat162*)(g_fb + (size_t)(r0 + rr) * 512))[cc];
            fs[rr * 512 + 2 * cc] = __low2float(v);
            fs[rr * 512 + 2 * cc + 1] = __high2float(v);
        }
        vs[row * 128 + c] = g_v1[(size_t)(r0 + row) * 128 + c];
        __syncthreads();
        float acc = bo[c];
        #pragma unroll 8
        for (int d = 0; d < 512; ++d) acc += fs[row * 512 + d] * __bfloat162float(Ws[d * 128 + c]);
        float x = vs[row * 128 + c] + acc, sm = x;
        for (int o = 16; o >= 1; o >>= 1) sm += __shfl_xor_sync(~0u, sm, o);
        if (!lane) red[row * 4 + wig] = sm;
        __syncthreads();
        float mu = (red[row * 4] + red[row * 4 + 1] + red[row * 4 + 2] + red[row * 4 + 3]) * (1.0f / 128.0f);
        float dv = x - mu, sq = dv * dv;
        for (int o = 16; o >= 1; o >>= 1) sq += __shfl_xor_sync(~0u, sq, o);
        if (!lane) red2[row * 4 + wig] = sq;
        __syncthreads();
        float var = (red2[row * 4] + red2[row * 4 + 1] + red2[row * 4 + 2] + red2[row * 4 + 3]) * (1.0f / 128.0f);
        int gr = r0 + row;
        float y = (dv * rsqrtf(var + 1e-5f) * g2s[c] + b2s[c]) * maskV[gr];
        outV[(size_t)gr * 128 + c] = y;
        g_hvb[(size_t)gr * 128 + c] = __float2bfloat16(y);
    }
}

extern "C" void kernel_launch(void* const* d_in, const int* in_sizes, int n_in,
                              void* d_out, int out_size) {
    const float* hV = (const float*)d_in[0];
    const float* hE = (const float*)d_in[1];
    const float* mV = (const float*)d_in[2];
    const int* Eidx = (const int*)d_in[3];
    const float* matt = (const float*)d_in[4];
    const float* W1 = (const float*)d_in[5],  *b1 = (const float*)d_in[6];
    const float* W2 = (const float*)d_in[7],  *b2 = (const float*)d_in[8];
    const float* W3 = (const float*)d_in[9],  *b3 = (const float*)d_in[10];
    const float* W11 = (const float*)d_in[11], *b11 = (const float*)d_in[12];
    const float* W12 = (const float*)d_in[13], *b12 = (const float*)d_in[14];
    const float* W13 = (const float*)d_in[15], *b13 = (const float*)d_in[16];
    const float* Win = (const float*)d_in[17], *bin = (const float*)d_in[18];
    const float* Wout = (const float*)d_in[19], *bout = (const float*)d_in[20];
    const float* g1 = (const float*)d_in[21], *bb1 = (const float*)d_in[22];
    const float* g2 = (const float*)d_in[23], *bb2 = (const float*)d_in[24];
    const float* g3 = (const float*)d_in[25], *bb3 = (const float*)d_in[26];
    float* outV = (float*)d_out;
    float* outE = (float*)d_out + HV_ELEMS;
    float* biasA; cudaGetSymbolAddress((void**)&biasA, g_biasA);
    float* biasC; cudaGetSymbolAddress((void**)&biasC, g_biasC);

    cudaFuncSetAttribute(kFold, cudaFuncAttributeMaxDynamicSharedMemorySize, KFOLD_SMEM);
    cudaFuncSetAttribute(kEdge, cudaFuncAttributeMaxDynamicSharedMemorySize, KE_SMEM);
    cudaFuncSetAttribute(kF1, cudaFuncAttributeMaxDynamicSharedMemorySize, SF1);
    cudaFuncSetAttribute(kF2, cudaFuncAttributeMaxDynamicSharedMemorySize, SF2);

    kFold<<<512, 256, KFOLD_SMEM>>>(hV, W1, b1, biasA, 1);
    kEdge<<<148, 256, KE_SMEM>>>(0, hE, W1 + 128 * 128, W2, W3, 128, b2, b3,
                                 biasA, matt, nullptr, nullptr, nullptr, nullptr);
    kLN1<<<NODES, 128>>>(hV, g1, bb1);
    kF1<<<NODES / 32, 512, SF1>>>(Win, bin);
    kF2<<<NODES / 32, 256, SF2>>>(Wout, bout, g2, bb2, mV, outV);
    kFold<<<512, 256, KFOLD_SMEM>>>(outV, W11, b11, biasC, 0);
    kEdge<<<148, 256, KE_SMEM>>>(1, hE, W11 + 128 * 128, W12, W13, 256, b12, b13,
                                 biasC, nullptr, Eidx, g3, bb3, outE);
}

// round 8
// speedup vs baseline: 2.0752x; 1.8767x over previous
#include <cuda_runtime.h>
#include <cuda_bf16.h>
#include <cstdint>

#define NODES 8192
#define H_ 128
#define K_ 48
#define EDGES (NODES * K_)
#define WTILES (EDGES / 16)      // 24576 warp-tiles of 16 edge rows
#define NTILES (NODES / 16)      // 512 warp-tiles of 16 node rows
#define HV_ELEMS (NODES * H_)
#define LDW 136

__device__ __align__(16) float         g_v1[NODES * H_];
__device__ __align__(16) __nv_bfloat16 g_fb[NODES * 512];
__device__ __align__(16) __nv_bfloat16 g_hvb[NODES * H_];
__device__ __align__(16) float         g_dh[NODES * H_];
__device__ __align__(16) float         g_biasA[NODES * H_];
__device__ __align__(16) float         g_biasC[NODES * H_];

static __device__ __forceinline__ unsigned su32(const void* p) {
    return (unsigned)__cvta_generic_to_shared(p);
}
static __device__ __forceinline__ float gelu_f(float x) {
    float u = 0.7978845608028654f * (x + 0.044715f * x * x * x), t;
    asm("tanh.approx.f32 %0, %1;" : "=f"(t) : "f"(u));
    return 0.5f * x * (1.0f + t);
}
static __device__ __forceinline__ uint32_t pk(float x, float y) {
    __nv_bfloat162 h = __floats2bfloat162_rn(x, y);
    return *(uint32_t*)&h;
}
static __device__ __forceinline__ void load_w(const float* g, __nv_bfloat16* s,
                                              int rows, int tid, int nthr) {
    int total4 = rows * 32;
    for (int i = tid; i < total4; i += nthr) {
        float4 w = ((const float4*)g)[i];
        int r = (i * 4) >> 7, c = (i * 4) & 127;
        *(__nv_bfloat162*)(s + r * LDW + c)     = __floats2bfloat162_rn(w.x, w.y);
        *(__nv_bfloat162*)(s + r * LDW + c + 2) = __floats2bfloat162_rn(w.z, w.w);
    }
}

#define MMA4(ac, a, b0, b1) \
    asm volatile("mma.sync.aligned.m16n8k16.row.col.f32.bf16.bf16.f32 " \
                 "{%0,%1,%2,%3},{%4,%5,%6,%7},{%8,%9},{%0,%1,%2,%3};" \
                 : "+f"((ac)[0]), "+f"((ac)[1]), "+f"((ac)[2]), "+f"((ac)[3]) \
                 : "r"((a)[0]), "r"((a)[1]), "r"((a)[2]), "r"((a)[3]), \
                   "r"(b0), "r"(b1))

static __device__ __forceinline__ void zero16(float acc[16][4]) {
    #pragma unroll
    for (int i = 0; i < 16; ++i)
        #pragma unroll
        for (int j = 0; j < 4; ++j) acc[i][j] = 0.0f;
}

// acc[16][4] += A(af frags)[16 x 16*NKT] * W[16*NKT x 128] from smem (wAddr incl. lane off)
template <int NKT>
static __device__ __forceinline__ void gemm_reg(const uint32_t* af, uint32_t wAddr,
                                                float acc[16][4]) {
    #pragma unroll
    for (int kt = 0; kt < NKT; ++kt) {
        #pragma unroll
        for (int nb = 0; nb < 8; ++nb) {
            uint32_t b[4];
            asm volatile("ldmatrix.sync.aligned.m8n8.x4.trans.shared.b16 {%0,%1,%2,%3},[%4];"
                         : "=r"(b[0]), "=r"(b[1]), "=r"(b[2]), "=r"(b[3])
                         : "r"(wAddr + kt * 4352 + nb * 32));
            MMA4(acc[2 * nb],     af + 4 * kt, b[0], b[1]);
            MMA4(acc[2 * nb + 1], af + 4 * kt, b[2], b[3]);
        }
    }
}

// A-frags (K=128) direct from 2 fp32 rows
static __device__ __forceinline__ void load_af_f32(const float* r0, const float* r1,
                                                   int tg, uint32_t af[32]) {
    #pragma unroll
    for (int kt = 0; kt < 8; ++kt) {
        int c = kt * 16 + 2 * tg;
        float2 v0 = *(const float2*)(r0 + c);
        float2 v1 = *(const float2*)(r1 + c);
        float2 v2 = *(const float2*)(r0 + c + 8);
        float2 v3 = *(const float2*)(r1 + c + 8);
        af[4 * kt]     = pk(v0.x, v0.y);
        af[4 * kt + 1] = pk(v1.x, v1.y);
        af[4 * kt + 2] = pk(v2.x, v2.y);
        af[4 * kt + 3] = pk(v3.x, v3.y);
    }
}
// A-frags (K=128) direct from 2 bf16 rows
static __device__ __forceinline__ void load_af_bf16(const __nv_bfloat16* r0,
                                                    const __nv_bfloat16* r1,
                                                    int tg, uint32_t af[32]) {
    #pragma unroll
    for (int kt = 0; kt < 8; ++kt) {
        int c = kt * 16 + 2 * tg;
        af[4 * kt]     = *(const uint32_t*)(r0 + c);
        af[4 * kt + 1] = *(const uint32_t*)(r1 + c);
        af[4 * kt + 2] = *(const uint32_t*)(r0 + c + 8);
        af[4 * kt + 3] = *(const uint32_t*)(r1 + c + 8);
    }
}
// af = bf16(gelu(acc + bias[col]))  -- C-frag layout == next A-frag layout
static __device__ __forceinline__ void pack_gelu(const float acc[16][4],
                                                 const float* bias, int tg,
                                                 uint32_t af[32]) {
    #pragma unroll
    for (int kt = 0; kt < 8; ++kt) {
        int n0 = 2 * kt, n1 = 2 * kt + 1;
        float2 bA = *(const float2*)(bias + n0 * 8 + 2 * tg);
        float2 bB = *(const float2*)(bias + n1 * 8 + 2 * tg);
        af[4 * kt]     = pk(gelu_f(acc[n0][0] + bA.x), gelu_f(acc[n0][1] + bA.y));
        af[4 * kt + 1] = pk(gelu_f(acc[n0][2] + bA.x), gelu_f(acc[n0][3] + bA.y));
        af[4 * kt + 2] = pk(gelu_f(acc[n1][0] + bB.x), gelu_f(acc[n1][1] + bB.y));
        af[4 * kt + 3] = pk(gelu_f(acc[n1][2] + bB.x), gelu_f(acc[n1][3] + bB.y));
    }
}

// ================= kFold =================
#define KFOLD_SMEM ((16384 + 2048) * 4)
__global__ void __launch_bounds__(256)
kFold(const float* __restrict__ x, const float* __restrict__ W,
      const float* __restrict__ b, float* __restrict__ out, int zdh) {
    extern __shared__ float sfold[];
    float* Ws = sfold;
    float* xs = sfold + 16384;
    int tid = threadIdx.x, n0 = blockIdx.x * 16;
    for (int i = tid; i < 16384; i += 256) Ws[i] = W[i];
    for (int i = tid; i < 2048; i += 256) xs[i] = x[(size_t)n0 * 128 + i];
    if (zdh) for (int i = tid; i < 2048; i += 256) g_dh[(size_t)n0 * 128 + i] = 0.0f;
    __syncthreads();
    int c = tid & 127, h = tid >> 7;
    for (int ni = 0; ni < 8; ++ni) {
        int nl = h * 8 + ni;
        float acc = b[c];
        #pragma unroll 8
        for (int d = 0; d < 128; ++d) acc += xs[nl * 128 + d] * Ws[d * 128 + c];
        out[(size_t)(n0 + nl) * 128 + c] = acc;
    }
}

// ================= kEdge: register-resident 3-layer MLP per warp-tile =================
#define KE_SMEM (69632 + 34816 + 34816 + 1024)
__global__ void __launch_bounds__(384, 1)
kEdge(int mode, const float* __restrict__ hE,
      const float* __restrict__ Wl1, const float* __restrict__ Wl2,
      const float* __restrict__ Wl3, int K1,
      const float* __restrict__ b2, const float* __restrict__ b3,
      const float* __restrict__ bias1, const float* __restrict__ matt,
      const int* __restrict__ Eidx, const float* __restrict__ g3,
      const float* __restrict__ bb3, float* __restrict__ outE) {
    extern __shared__ char sm[];
    __nv_bfloat16* W1s = (__nv_bfloat16*)sm;
    __nv_bfloat16* W2s = (__nv_bfloat16*)(sm + K1 * 272);
    __nv_bfloat16* W3s = (__nv_bfloat16*)(sm + K1 * 272 + 34816);
    float* bs = (float*)(sm + K1 * 272 + 69632);
    int tid = threadIdx.x, lane = tid & 31, warp = tid >> 5;
    int gid = lane >> 2, tg = lane & 3;

    load_w(Wl1, W1s, K1, tid, 384);
    load_w(Wl2, W2s, 128, tid, 384);
    load_w(Wl3, W3s, 128, tid, 384);
    if (tid < 128) { bs[tid] = b2[tid]; bs[128 + tid] = b3[tid]; }
    __syncthreads();
    float* b2s = bs; float* b3s = bs + 128;

    uint32_t loff = (uint32_t)(((lane & 15) * LDW + ((lane >> 4) * 8)) * 2);
    uint32_t w1Addr = su32(W1s) + loff;
    uint32_t w2Addr = su32(W2s) + loff;
    uint32_t w3Addr = su32(W3s) + loff;

    for (int wt = blockIdx.x * 12 + warp; wt < WTILES; wt += gridDim.x * 12) {
        int rowbase = wt * 16;
        int r0 = rowbase + gid, r1 = r0 + 8;
        int node = rowbase / 48;
        uint32_t af[32];
        float acc[16][4];

        load_af_f32(hE + (size_t)r0 * 128, hE + (size_t)r1 * 128, tg, af);
        zero16(acc);
        gemm_reg<8>(af, w1Addr, acc);
        if (mode) {
            int bbase = (rowbase / 98304) * 2048;
            int nb0 = bbase + Eidx[r0], nb1 = bbase + Eidx[r1];
            load_af_bf16(g_hvb + (size_t)nb0 * 128, g_hvb + (size_t)nb1 * 128, tg, af);
            gemm_reg<8>(af, w1Addr + 128 * 272, acc);
        }
        pack_gelu(acc, bias1 + (size_t)node * 128, tg, af);
        zero16(acc);
        gemm_reg<8>(af, w2Addr, acc);
        pack_gelu(acc, b2s, tg, af);
        zero16(acc);
        gemm_reg<8>(af, w3Addr, acc);

        if (mode == 0) {
            float m0 = __ldg(matt + r0), m1 = __ldg(matt + r1);
            float s[32];
            #pragma unroll
            for (int nt = 0; nt < 16; ++nt) {
                float2 b = *(const float2*)(b3s + nt * 8 + 2 * tg);
                s[2 * nt]     = (acc[nt][0] + b.x) * m0 + (acc[nt][2] + b.x) * m1;
                s[2 * nt + 1] = (acc[nt][1] + b.y) * m0 + (acc[nt][3] + b.y) * m1;
            }
            #pragma unroll
            for (int o = 4; o < 32; o <<= 1)
                #pragma unroll
                for (int i = 0; i < 32; ++i) s[i] += __shfl_xor_sync(~0u, s[i], o);
            if (lane < 4) {
                float* dst = g_dh + (size_t)node * 128;
                #pragma unroll
                for (int nt = 0; nt < 16; ++nt) {
                    atomicAdd(dst + nt * 8 + 2 * lane,     s[2 * nt]);
                    atomicAdd(dst + nt * 8 + 2 * lane + 1, s[2 * nt + 1]);
                }
            }
        } else {
            const float* e0 = hE + (size_t)r0 * 128;
            const float* e1 = hE + (size_t)r1 * 128;
            float sum0 = 0.f, sq0 = 0.f, sum1 = 0.f, sq1 = 0.f;
            #pragma unroll
            for (int nt = 0; nt < 16; ++nt) {
                int c = nt * 8 + 2 * tg;
                float2 b  = *(const float2*)(b3s + c);
                float2 h0 = *(const float2*)(e0 + c);
                float2 h1 = *(const float2*)(e1 + c);
                acc[nt][0] += b.x + h0.x; acc[nt][1] += b.y + h0.y;
                acc[nt][2] += b.x + h1.x; acc[nt][3] += b.y + h1.y;
                sum0 += acc[nt][0] + acc[nt][1];
                sq0  += acc[nt][0] * acc[nt][0] + acc[nt][1] * acc[nt][1];
                sum1 += acc[nt][2] + acc[nt][3];
                sq1  += acc[nt][2] * acc[nt][2] + acc[nt][3] * acc[nt][3];
            }
            #pragma unroll
            for (int o = 1; o < 4; o <<= 1) {
                sum0 += __shfl_xor_sync(~0u, sum0, o);
                sq0  += __shfl_xor_sync(~0u, sq0, o);
                sum1 += __shfl_xor_sync(~0u, sum1, o);
                sq1  += __shfl_xor_sync(~0u, sq1, o);
            }
            float mu0 = sum0 * (1.0f / 128.0f);
            float iv0 = rsqrtf(sq0 * (1.0f / 128.0f) - mu0 * mu0 + 1e-5f);
            float mu1 = sum1 * (1.0f / 128.0f);
            float iv1 = rsqrtf(sq1 * (1.0f / 128.0f) - mu1 * mu1 + 1e-5f);
            float* o0 = outE + (size_t)r0 * 128;
            float* o1 = outE + (size_t)r1 * 128;
            #pragma unroll
            for (int nt = 0; nt < 16; ++nt) {
                int c = nt * 8 + 2 * tg;
                float gx = __ldg(g3 + c), gy = __ldg(g3 + c + 1);
                float bx = __ldg(bb3 + c), by = __ldg(bb3 + c + 1);
                float2 v0 = { (acc[nt][0] - mu0) * iv0 * gx + bx,
                              (acc[nt][1] - mu0) * iv0 * gy + by };
                float2 v1 = { (acc[nt][2] - mu1) * iv1 * gx + bx,
                              (acc[nt][3] - mu1) * iv1 * gy + by };
                *(float2*)(o0 + c) = v0;
                *(float2*)(o1 + c) = v1;
            }
        }
    }
}

// ================= kLN1 =================
__global__ void __launch_bounds__(128)
kLN1(const float* __restrict__ hV, const float* __restrict__ g1, const float* __restrict__ b1) {
    __shared__ float red[8];
    int n = blockIdx.x, c = threadIdx.x, lane = c & 31, w = c >> 5;
    float x = hV[(size_t)n * 128 + c] + g_dh[(size_t)n * 128 + c] * (1.0f / 30.0f);
    float s = x;
    for (int o = 16; o >= 1; o >>= 1) s += __shfl_xor_sync(~0u, s, o);
    if (!lane) red[w] = s;
    __syncthreads();
    float mu = (red[0] + red[1] + red[2] + red[3]) * (1.0f / 128.0f);
    float d = x - mu, q = d * d;
    for (int o = 16; o >= 1; o >>= 1) q += __shfl_xor_sync(~0u, q, o);
    if (!lane) red[4 + w] = q;
    __syncthreads();
    float var = (red[4] + red[5] + red[6] + red[7]) * (1.0f / 128.0f);
    g_v1[(size_t)n * 128 + c] = d * rsqrtf(var + 1e-5f) * g1[c] + b1[c];
}

// ================= kF1 (tensor): g_fb = gelu(v1 @ Win + bin) =================
#define SF1 (4 * 34816 + 2048)
__global__ void __launch_bounds__(384, 1)
kF1(const float* __restrict__ Win, const float* __restrict__ bin) {
    extern __shared__ char sm[];
    float* bin_s = (float*)(sm + 4 * 34816);
    int tid = threadIdx.x, lane = tid & 31, warp = tid >> 5;
    int gid = lane >> 2, tg = lane & 3;
    for (int i = tid; i < 16384; i += 384) {
        float4 w = ((const float4*)Win)[i];
        int k = i >> 7, n = (i * 4) & 511;
        __nv_bfloat16* dst = (__nv_bfloat16*)(sm + (n >> 7) * 34816);
        int cc = n & 127;
        *(__nv_bfloat162*)(dst + k * LDW + cc)     = __floats2bfloat162_rn(w.x, w.y);
        *(__nv_bfloat162*)(dst + k * LDW + cc + 2) = __floats2bfloat162_rn(w.z, w.w);
    }
    for (int i = tid; i < 512; i += 384) bin_s[i] = bin[i];
    __syncthreads();
    uint32_t loff = (uint32_t)(((lane & 15) * LDW + ((lane >> 4) * 8)) * 2);

    for (int wt = blockIdx.x * 12 + warp; wt < NTILES; wt += gridDim.x * 12) {
        int r0 = wt * 16 + gid, r1 = r0 + 8;
        uint32_t af[32];
        float acc[16][4];
        load_af_f32(g_v1 + (size_t)r0 * 128, g_v1 + (size_t)r1 * 128, tg, af);
        #pragma unroll
        for (int ng = 0; ng < 4; ++ng) {
            zero16(acc);
            gemm_reg<8>(af, su32(sm + ng * 34816) + loff, acc);
            #pragma unroll
            for (int nt = 0; nt < 16; ++nt) {
                int cg = ng * 128 + nt * 8 + 2 * tg;
                float2 b = *(const float2*)(bin_s + cg);
                *(uint32_t*)(g_fb + (size_t)r0 * 512 + cg) =
                    pk(gelu_f(acc[nt][0] + b.x), gelu_f(acc[nt][1] + b.y));
                *(uint32_t*)(g_fb + (size_t)r1 * 512 + cg) =
                    pk(gelu_f(acc[nt][2] + b.x), gelu_f(acc[nt][3] + b.y));
            }
        }
    }
}

// ================= kF2 (tensor): outV = mask * LN2(v1 + g_fb @ Wout + bout) ==========
#define SF2 (512 * 272 + 1536)
__global__ void __launch_bounds__(384, 1)
kF2(const float* __restrict__ Wout, const float* __restrict__ bout,
    const float* __restrict__ g2, const float* __restrict__ bb2,
    const float* __restrict__ maskV, float* __restrict__ outV) {
    extern __shared__ char sm[];
    __nv_bfloat16* Ws = (__nv_bfloat16*)sm;
    float* bs = (float*)(sm + 512 * 272);
    int tid = threadIdx.x, lane = tid & 31, warp = tid >> 5;
    int gid = lane >> 2, tg = lane & 3;
    load_w(Wout, Ws, 512, tid, 384);
    if (tid < 128) { bs[tid] = bout[tid]; bs[128 + tid] = g2[tid]; bs[256 + tid] = bb2[tid]; }
    __syncthreads();
    float* bo = bs; float* g2s = bs + 128; float* b2s = bs + 256;
    uint32_t loff = (uint32_t)(((lane & 15) * LDW + ((lane >> 4) * 8)) * 2);
    uint32_t wAddr = su32(Ws) + loff;

    for (int wt = blockIdx.x * 12 + warp; wt < NTILES; wt += gridDim.x * 12) {
        int r0 = wt * 16 + gid, r1 = r0 + 8;
        const __nv_bfloat16* f0 = g_fb + (size_t)r0 * 512;
        const __nv_bfloat16* f1 = g_fb + (size_t)r1 * 512;
        float acc[16][4];
        zero16(acc);
        #pragma unroll 4
        for (int kt = 0; kt < 32; ++kt) {
            uint32_t a[4];
            int c = kt * 16 + 2 * tg;
            a[0] = *(const uint32_t*)(f0 + c);
            a[1] = *(const uint32_t*)(f1 + c);
            a[2] = *(const uint32_t*)(f0 + c + 8);
            a[3] = *(const uint32_t*)(f1 + c + 8);
            #pragma unroll
            for (int nb = 0; nb < 8; ++nb) {
                uint32_t b[4];
                asm volatile("ldmatrix.sync.aligned.m8n8.x4.trans.shared.b16 {%0,%1,%2,%3},[%4];"
                             : "=r"(b[0]), "=r"(b[1]), "=r"(b[2]), "=r"(b[3])
                             : "r"(wAddr + kt * 4352 + nb * 32));
                MMA4(acc[2 * nb],     a, b[0], b[1]);
                MMA4(acc[2 * nb + 1], a, b[2], b[3]);
            }
        }
        const float* v0 = g_v1 + (size_t)r0 * 128;
        const float* v1 = g_v1 + (size_t)r1 * 128;
        float sum0 = 0.f, sq0 = 0.f, sum1 = 0.f, sq1 = 0.f;
        #pragma unroll
        for (int nt = 0; nt < 16; ++nt) {
            int c = nt * 8 + 2 * tg;
            float2 b  = *(const float2*)(bo + c);
            float2 h0 = *(const float2*)(v0 + c);
            float2 h1 = *(const float2*)(v1 + c);
            acc[nt][0] += b.x + h0.x; acc[nt][1] += b.y + h0.y;
            acc[nt][2] += b.x + h1.x; acc[nt][3] += b.y + h1.y;
            sum0 += acc[nt][0] + acc[nt][1];
            sq0  += acc[nt][0] * acc[nt][0] + acc[nt][1] * acc[nt][1];
            sum1 += acc[nt][2] + acc[nt][3];
            sq1  += acc[nt][2] * acc[nt][2] + acc[nt][3] * acc[nt][3];
        }
        #pragma unroll
        for (int o = 1; o < 4; o <<= 1) {
            sum0 += __shfl_xor_sync(~0u, sum0, o);
            sq0  += __shfl_xor_sync(~0u, sq0, o);
            sum1 += __shfl_xor_sync(~0u, sum1, o);
            sq1  += __shfl_xor_sync(~0u, sq1, o);
        }
        float mu0 = sum0 * (1.0f / 128.0f);
        float iv0 = rsqrtf(sq0 * (1.0f / 128.0f) - mu0 * mu0 + 1e-5f);
        float mu1 = sum1 * (1.0f / 128.0f);
        float iv1 = rsqrtf(sq1 * (1.0f / 128.0f) - mu1 * mu1 + 1e-5f);
        float mv0 = __ldg(maskV + r0), mv1 = __ldg(maskV + r1);
        #pragma unroll
        for (int nt = 0; nt < 16; ++nt) {
            int c = nt * 8 + 2 * tg;
            float gx = g2s[c], gy = g2s[c + 1], bx = b2s[c], by = b2s[c + 1];
            float2 y0 = { ((acc[nt][0] - mu0) * iv0 * gx + bx) * mv0,
                          ((acc[nt][1] - mu0) * iv0 * gy + by) * mv0 };
            float2 y1 = { ((acc[nt][2] - mu1) * iv1 * gx + bx) * mv1,
                          ((acc[nt][3] - mu1) * iv1 * gy + by) * mv1 };
            *(float2*)(outV + (size_t)r0 * 128 + c) = y0;
            *(float2*)(outV + (size_t)r1 * 128 + c) = y1;
            *(uint32_t*)(g_hvb + (size_t)r0 * 128 + c) = pk(y0.x, y0.y);
            *(uint32_t*)(g_hvb + (size_t)r1 * 128 + c) = pk(y1.x, y1.y);
        }
    }
}

extern "C" void kernel_launch(void* const* d_in, const int* in_sizes, int n_in,
                              void* d_out, int out_size) {
    const float* hV = (const float*)d_in[0];
    const float* hE = (const float*)d_in[1];
    const float* mV = (const float*)d_in[2];
    const int* Eidx = (const int*)d_in[3];
    const float* matt = (const float*)d_in[4];
    const float* W1 = (const float*)d_in[5],  *b1 = (const float*)d_in[6];
    const float* W2 = (const float*)d_in[7],  *b2 = (const float*)d_in[8];
    const float* W3 = (const float*)d_in[9],  *b3 = (const float*)d_in[10];
    const float* W11 = (const float*)d_in[11], *b11 = (const float*)d_in[12];
    const float* W12 = (const float*)d_in[13], *b12 = (const float*)d_in[14];
    const float* W13 = (const float*)d_in[15], *b13 = (const float*)d_in[16];
    const float* Win = (const float*)d_in[17], *bin = (const float*)d_in[18];
    const float* Wout = (const float*)d_in[19], *bout = (const float*)d_in[20];
    const float* g1 = (const float*)d_in[21], *bb1 = (const float*)d_in[22];
    const float* g2 = (const float*)d_in[23], *bb2 = (const float*)d_in[24];
    const float* g3 = (const float*)d_in[25], *bb3 = (const float*)d_in[26];
    float* outV = (float*)d_out;
    float* outE = (float*)d_out + HV_ELEMS;
    float* biasA; cudaGetSymbolAddress((void**)&biasA, g_biasA);
    float* biasC; cudaGetSymbolAddress((void**)&biasC, g_biasC);

    cudaFuncSetAttribute(kFold, cudaFuncAttributeMaxDynamicSharedMemorySize, KFOLD_SMEM);
    cudaFuncSetAttribute(kEdge, cudaFuncAttributeMaxDynamicSharedMemorySize, KE_SMEM);
    cudaFuncSetAttribute(kF1, cudaFuncAttributeMaxDynamicSharedMemorySize, SF1);
    cudaFuncSetAttribute(kF2, cudaFuncAttributeMaxDynamicSharedMemorySize, SF2);

    kFold<<<512, 256, KFOLD_SMEM>>>(hV, W1, b1, biasA, 1);
    kEdge<<<148, 384, 104448 + 1024>>>(0, hE, W1 + 128 * 128, W2, W3, 128, b2, b3,
                                       biasA, matt, nullptr, nullptr, nullptr, nullptr);
    kLN1<<<NODES, 128>>>(hV, g1, bb1);
    kF1<<<43, 384, SF1>>>(Win, bin);
    kF2<<<43, 384, SF2>>>(Wout, bout, g2, bb2, mV, outV);
    kFold<<<512, 256, KFOLD_SMEM>>>(outV, W11, b11, biasC, 0);
    kEdge<<<148, 384, KE_SMEM>>>(1, hE, W11 + 128 * 128, W12, W13, 256, b12, b13,
                                 biasC, nullptr, Eidx, g3, bb3, outE);
}

// round 9
// speedup vs baseline: 2.3895x; 1.1514x over previous
#include <cuda_runtime.h>
#include <cuda_bf16.h>
#include <cstdint>

#define NODES 8192
#define H_ 128
#define K_ 48
#define EDGES (NODES * K_)
#define WTILES (EDGES / 16)      // 24576 edge warp-tiles
#define NTILES (NODES / 16)      // 512 node warp-tiles
#define HV_ELEMS (NODES * H_)
#define LDW 136

__device__ __align__(16) float         g_v1[NODES * H_];
__device__ __align__(16) __nv_bfloat16 g_fb[NODES * 512];
__device__ __align__(16) __nv_bfloat16 g_hvb[NODES * H_];
__device__ __align__(16) float         g_dh[NODES * H_];
__device__ __align__(16) float         g_biasA[NODES * H_];
__device__ __align__(16) float         g_biasC[NODES * H_];

static __device__ __forceinline__ unsigned su32(const void* p) {
    return (unsigned)__cvta_generic_to_shared(p);
}
static __device__ __forceinline__ float gelu_f(float x) {
    float u = 0.7978845608028654f * (x + 0.044715f * x * x * x), t;
    asm("tanh.approx.f32 %0, %1;" : "=f"(t) : "f"(u));
    return 0.5f * x * (1.0f + t);
}
static __device__ __forceinline__ uint32_t pk(float x, float y) {
    __nv_bfloat162 h = __floats2bfloat162_rn(x, y);
    return *(uint32_t*)&h;
}
static __device__ __forceinline__ void load_w(const float* g, __nv_bfloat16* s,
                                              int rows, int tid, int nthr) {
    int total4 = rows * 32;
    for (int i = tid; i < total4; i += nthr) {
        float4 w = ((const float4*)g)[i];
        int r = (i * 4) >> 7, c = (i * 4) & 127;
        *(__nv_bfloat162*)(s + r * LDW + c)     = __floats2bfloat162_rn(w.x, w.y);
        *(__nv_bfloat162*)(s + r * LDW + c + 2) = __floats2bfloat162_rn(w.z, w.w);
    }
}

#define MMA4(ac, a, b0, b1) \
    asm volatile("mma.sync.aligned.m16n8k16.row.col.f32.bf16.bf16.f32 " \
                 "{%0,%1,%2,%3},{%4,%5,%6,%7},{%8,%9},{%0,%1,%2,%3};" \
                 : "+f"((ac)[0]), "+f"((ac)[1]), "+f"((ac)[2]), "+f"((ac)[3]) \
                 : "r"((a)[0]), "r"((a)[1]), "r"((a)[2]), "r"((a)[3]), \
                   "r"(b0), "r"(b1))

static __device__ __forceinline__ void zero16(float acc[16][4]) {
    #pragma unroll
    for (int i = 0; i < 16; ++i)
        #pragma unroll
        for (int j = 0; j < 4; ++j) acc[i][j] = 0.0f;
}

// acc[16][4] += A(frags)[16 x 16*NKT] * W[16*NKT x 128] (wAddr incl. lane offset)
template <int NKT>
static __device__ __forceinline__ void gemm_reg(const uint32_t* af, uint32_t wAddr,
                                                float acc[16][4]) {
    #pragma unroll
    for (int kt = 0; kt < NKT; ++kt) {
        #pragma unroll
        for (int nb = 0; nb < 8; ++nb) {
            uint32_t b[4];
            asm volatile("ldmatrix.sync.aligned.m8n8.x4.trans.shared.b16 {%0,%1,%2,%3},[%4];"
                         : "=r"(b[0]), "=r"(b[1]), "=r"(b[2]), "=r"(b[3])
                         : "r"(wAddr + kt * 4352 + nb * 32));
            MMA4(acc[2 * nb],     af + 4 * kt, b[0], b[1]);
            MMA4(acc[2 * nb + 1], af + 4 * kt, b[2], b[3]);
        }
    }
}

static __device__ __forceinline__ void load_af_f32(const float* r0, const float* r1,
                                                   int tg, uint32_t af[32]) {
    #pragma unroll
    for (int kt = 0; kt < 8; ++kt) {
        int c = kt * 16 + 2 * tg;
        float2 v0 = *(const float2*)(r0 + c);
        float2 v1 = *(const float2*)(r1 + c);
        float2 v2 = *(const float2*)(r0 + c + 8);
        float2 v3 = *(const float2*)(r1 + c + 8);
        af[4 * kt]     = pk(v0.x, v0.y);
        af[4 * kt + 1] = pk(v1.x, v1.y);
        af[4 * kt + 2] = pk(v2.x, v2.y);
        af[4 * kt + 3] = pk(v3.x, v3.y);
    }
}
static __device__ __forceinline__ void load_af_bf16(const __nv_bfloat16* r0,
                                                    const __nv_bfloat16* r1,
                                                    int tg, uint32_t af[32]) {
    #pragma unroll
    for (int kt = 0; kt < 8; ++kt) {
        int c = kt * 16 + 2 * tg;
        af[4 * kt]     = *(const uint32_t*)(r0 + c);
        af[4 * kt + 1] = *(const uint32_t*)(r1 + c);
        af[4 * kt + 2] = *(const uint32_t*)(r0 + c + 8);
        af[4 * kt + 3] = *(const uint32_t*)(r1 + c + 8);
    }
}
static __device__ __forceinline__ void pack_gelu(const float acc[16][4],
                                                 const float* bias, int tg,
                                                 uint32_t af[32]) {
    #pragma unroll
    for (int kt = 0; kt < 8; ++kt) {
        int n0 = 2 * kt, n1 = 2 * kt + 1;
        float2 bA = *(const float2*)(bias + n0 * 8 + 2 * tg);
        float2 bB = *(const float2*)(bias + n1 * 8 + 2 * tg);
        af[4 * kt]     = pk(gelu_f(acc[n0][0] + bA.x), gelu_f(acc[n0][1] + bA.y));
        af[4 * kt + 1] = pk(gelu_f(acc[n0][2] + bA.x), gelu_f(acc[n0][3] + bA.y));
        af[4 * kt + 2] = pk(gelu_f(acc[n1][0] + bB.x), gelu_f(acc[n1][1] + bB.y));
        af[4 * kt + 3] = pk(gelu_f(acc[n1][2] + bB.x), gelu_f(acc[n1][3] + bB.y));
    }
}

// ================= kFoldT (tensor): out = b + x @ W[0:128]; opt zero g_dh ============
#define SFOLD (34816 + 512)
__global__ void __launch_bounds__(128, 1)
kFoldT(const float* __restrict__ x, const float* __restrict__ W,
       const float* __restrict__ b, float* __restrict__ out, int zdh) {
    extern __shared__ char sm[];
    __nv_bfloat16* Ws = (__nv_bfloat16*)sm;
    float* bsm = (float*)(sm + 34816);
    int tid = threadIdx.x, lane = tid & 31, warp = tid >> 5;
    int gid = lane >> 2, tg = lane & 3;
    load_w(W, Ws, 128, tid, 128);
    if (tid < 128) bsm[tid] = b[tid];
    __syncthreads();
    uint32_t loff = (uint32_t)(((lane & 15) * LDW + ((lane >> 4) * 8)) * 2);
    uint32_t wAddr = su32(Ws) + loff;
    for (int wt = blockIdx.x * 4 + warp; wt < NTILES; wt += gridDim.x * 4) {
        int r0 = wt * 16 + gid, r1 = r0 + 8;
        uint32_t af[32];
        float acc[16][4];
        load_af_f32(x + (size_t)r0 * 128, x + (size_t)r1 * 128, tg, af);
        zero16(acc);
        gemm_reg<8>(af, wAddr, acc);
        #pragma unroll
        for (int nt = 0; nt < 16; ++nt) {
            int c = nt * 8 + 2 * tg;
            float2 bb = *(const float2*)(bsm + c);
            float2 v0 = { acc[nt][0] + bb.x, acc[nt][1] + bb.y };
            float2 v1 = { acc[nt][2] + bb.x, acc[nt][3] + bb.y };
            *(float2*)(out + (size_t)r0 * 128 + c) = v0;
            *(float2*)(out + (size_t)r1 * 128 + c) = v1;
            if (zdh) {
                float2 z = { 0.f, 0.f };
                *(float2*)(g_dh + (size_t)r0 * 128 + c) = z;
                *(float2*)(g_dh + (size_t)r1 * 128 + c) = z;
            }
        }
    }
}

// ================= kEdge: register-resident 3-layer MLP, 16 warps, prefetch ==========
#define KE_SMEM (69632 + 34816 + 34816 + 1024)
__global__ void __launch_bounds__(512, 1)
kEdge(int mode, const float* __restrict__ hE,
      const float* __restrict__ Wl1, const float* __restrict__ Wl2,
      const float* __restrict__ Wl3, int K1,
      const float* __restrict__ b2, const float* __restrict__ b3,
      const float* __restrict__ bias1, const float* __restrict__ matt,
      const int* __restrict__ Eidx, const float* __restrict__ g3,
      const float* __restrict__ bb3, float* __restrict__ outE) {
    extern __shared__ char sm[];
    __nv_bfloat16* W1s = (__nv_bfloat16*)sm;
    __nv_bfloat16* W2s = (__nv_bfloat16*)(sm + K1 * 272);
    __nv_bfloat16* W3s = (__nv_bfloat16*)(sm + K1 * 272 + 34816);
    float* bs = (float*)(sm + K1 * 272 + 69632);
    int tid = threadIdx.x, lane = tid & 31, warp = tid >> 5;
    int gid = lane >> 2, tg = lane & 3;

    load_w(Wl1, W1s, K1, tid, 512);
    load_w(Wl2, W2s, 128, tid, 512);
    load_w(Wl3, W3s, 128, tid, 512);
    if (tid < 128) { bs[tid] = b2[tid]; bs[128 + tid] = b3[tid]; }
    __syncthreads();
    float* b2s = bs; float* b3s = bs + 128;

    uint32_t loff = (uint32_t)(((lane & 15) * LDW + ((lane >> 4) * 8)) * 2);
    uint32_t w1Addr = su32(W1s) + loff;
    uint32_t w2Addr = su32(W2s) + loff;
    uint32_t w3Addr = su32(W3s) + loff;

    const int stride = gridDim.x * 16;
    int wt = blockIdx.x * 16 + warp;
    uint32_t af[32];
    float acc[16][4];
    if (wt < WTILES) {
        int r0 = wt * 16 + gid;
        load_af_f32(hE + (size_t)r0 * 128, hE + (size_t)(r0 + 8) * 128, tg, af);
    }
    while (wt < WTILES) {
        int rowbase = wt * 16;
        int r0 = rowbase + gid, r1 = r0 + 8;
        int node = rowbase / 48;
        int nb0 = 0, nb1 = 0;
        if (mode) {   // hoist gather indices so loads overlap gemm1
            int bbase = (rowbase / 98304) * 2048;
            nb0 = bbase + Eidx[r0];
            nb1 = bbase + Eidx[r1];
        }
        zero16(acc);
        gemm_reg<8>(af, w1Addr, acc);
        if (mode) {
            load_af_bf16(g_hvb + (size_t)nb0 * 128, g_hvb + (size_t)nb1 * 128, tg, af);
            gemm_reg<8>(af, w1Addr + 128 * 272, acc);
        }
        pack_gelu(acc, bias1 + (size_t)node * 128, tg, af);
        zero16(acc);
        gemm_reg<8>(af, w2Addr, acc);
        pack_gelu(acc, b2s, tg, af);
        zero16(acc);
        gemm_reg<8>(af, w3Addr, acc);

        int wtn = wt + stride;
        if (wtn < WTILES) {   // prefetch next tile's hE frags during epilogue
            int rn = wtn * 16 + gid;
            load_af_f32(hE + (size_t)rn * 128, hE + (size_t)(rn + 8) * 128, tg, af);
        }

        if (mode == 0) {
            float m0 = __ldg(matt + r0), m1 = __ldg(matt + r1);
            #pragma unroll
            for (int nt = 0; nt < 16; ++nt) {
                float2 b = *(const float2*)(b3s + nt * 8 + 2 * tg);
                acc[nt][0] = (acc[nt][0] + b.x) * m0 + (acc[nt][2] + b.x) * m1;
                acc[nt][1] = (acc[nt][1] + b.y) * m0 + (acc[nt][3] + b.y) * m1;
            }
            #pragma unroll
            for (int o = 4; o < 32; o <<= 1)
                #pragma unroll
                for (int nt = 0; nt < 16; ++nt) {
                    acc[nt][0] += __shfl_xor_sync(~0u, acc[nt][0], o);
                    acc[nt][1] += __shfl_xor_sync(~0u, acc[nt][1], o);
                }
            if (lane < 4) {
                float* dst = g_dh + (size_t)node * 128;
                #pragma unroll
                for (int nt = 0; nt < 16; ++nt) {
                    atomicAdd(dst + nt * 8 + 2 * lane,     acc[nt][0]);
                    atomicAdd(dst + nt * 8 + 2 * lane + 1, acc[nt][1]);
                }
            }
        } else {
            const float* e0 = hE + (size_t)r0 * 128;
            const float* e1 = hE + (size_t)r1 * 128;
            float sum0 = 0.f, sq0 = 0.f, sum1 = 0.f, sq1 = 0.f;
            #pragma unroll
            for (int nt = 0; nt < 16; ++nt) {
                int c = nt * 8 + 2 * tg;
                float2 b  = *(const float2*)(b3s + c);
                float2 h0 = *(const float2*)(e0 + c);
                float2 h1 = *(const float2*)(e1 + c);
                acc[nt][0] += b.x + h0.x; acc[nt][1] += b.y + h0.y;
                acc[nt][2] += b.x + h1.x; acc[nt][3] += b.y + h1.y;
                sum0 += acc[nt][0] + acc[nt][1];
                sq0  += acc[nt][0] * acc[nt][0] + acc[nt][1] * acc[nt][1];
                sum1 += acc[nt][2] + acc[nt][3];
                sq1  += acc[nt][2] * acc[nt][2] + acc[nt][3] * acc[nt][3];
            }
            #pragma unroll
            for (int o = 1; o < 4; o <<= 1) {
                sum0 += __shfl_xor_sync(~0u, sum0, o);
                sq0  += __shfl_xor_sync(~0u, sq0, o);
                sum1 += __shfl_xor_sync(~0u, sum1, o);
                sq1  += __shfl_xor_sync(~0u, sq1, o);
            }
            float mu0 = sum0 * (1.0f / 128.0f);
            float iv0 = rsqrtf(sq0 * (1.0f / 128.0f) - mu0 * mu0 + 1e-5f);
            float mu1 = sum1 * (1.0f / 128.0f);
            float iv1 = rsqrtf(sq1 * (1.0f / 128.0f) - mu1 * mu1 + 1e-5f);
            float* o0 = outE + (size_t)r0 * 128;
            float* o1 = outE + (size_t)r1 * 128;
            #pragma unroll
            for (int nt = 0; nt < 16; ++nt) {
                int c = nt * 8 + 2 * tg;
                float gx = __ldg(g3 + c), gy = __ldg(g3 + c + 1);
                float bx = __ldg(bb3 + c), by = __ldg(bb3 + c + 1);
                float2 v0 = { (acc[nt][0] - mu0) * iv0 * gx + bx,
                              (acc[nt][1] - mu0) * iv0 * gy + by };
                float2 v1 = { (acc[nt][2] - mu1) * iv1 * gx + bx,
                              (acc[nt][3] - mu1) * iv1 * gy + by };
                *(float2*)(o0 + c) = v0;
                *(float2*)(o1 + c) = v1;
            }
        }
        wt = wtn;
    }
}

// ================= kLN1 =================
__global__ void __launch_bounds__(128)
kLN1(const float* __restrict__ hV, const float* __restrict__ g1, const float* __restrict__ b1) {
    __shared__ float red[8];
    int n = blockIdx.x, c = threadIdx.x, lane = c & 31, w = c >> 5;
    float x = hV[(size_t)n * 128 + c] + g_dh[(size_t)n * 128 + c] * (1.0f / 30.0f);
    float s = x;
    for (int o = 16; o >= 1; o >>= 1) s += __shfl_xor_sync(~0u, s, o);
    if (!lane) red[w] = s;
    __syncthreads();
    float mu = (red[0] + red[1] + red[2] + red[3]) * (1.0f / 128.0f);
    float d = x - mu, q = d * d;
    for (int o = 16; o >= 1; o >>= 1) q += __shfl_xor_sync(~0u, q, o);
    if (!lane) red[4 + w] = q;
    __syncthreads();
    float var = (red[4] + red[5] + red[6] + red[7]) * (1.0f / 128.0f);
    g_v1[(size_t)n * 128 + c] = d * rsqrtf(var + 1e-5f) * g1[c] + b1[c];
}

// ================= kF1 (tensor): g_fb = gelu(v1 @ Win + bin) =================
#define SF1 (4 * 34816 + 2048)
__global__ void __launch_bounds__(128, 1)
kF1(const float* __restrict__ Win, const float* __restrict__ bin) {
    extern __shared__ char sm[];
    float* bin_s = (float*)(sm + 4 * 34816);
    int tid = threadIdx.x, lane = tid & 31, warp = tid >> 5;
    int gid = lane >> 2, tg = lane & 3;
    for (int i = tid; i < 16384; i += 128) {
        float4 w = ((const float4*)Win)[i];
        int k = i >> 7, n = (i * 4) & 511;
        __nv_bfloat16* dst = (__nv_bfloat16*)(sm + (n >> 7) * 34816);
        int cc = n & 127;
        *(__nv_bfloat162*)(dst + k * LDW + cc)     = __floats2bfloat162_rn(w.x, w.y);
        *(__nv_bfloat162*)(dst + k * LDW + cc + 2) = __floats2bfloat162_rn(w.z, w.w);
    }
    for (int i = tid; i < 512; i += 128) bin_s[i] = bin[i];
    __syncthreads();
    uint32_t loff = (uint32_t)(((lane & 15) * LDW + ((lane >> 4) * 8)) * 2);

    for (int wt = blockIdx.x * 4 + warp; wt < NTILES; wt += gridDim.x * 4) {
        int r0 = wt * 16 + gid, r1 = r0 + 8;
        uint32_t af[32];
        float acc[16][4];
        load_af_f32(g_v1 + (size_t)r0 * 128, g_v1 + (size_t)r1 * 128, tg, af);
        #pragma unroll
        for (int ng = 0; ng < 4; ++ng) {
            zero16(acc);
            gemm_reg<8>(af, su32(sm + ng * 34816) + loff, acc);
            #pragma unroll
            for (int nt = 0; nt < 16; ++nt) {
                int cg = ng * 128 + nt * 8 + 2 * tg;
                float2 b = *(const float2*)(bin_s + cg);
                *(uint32_t*)(g_fb + (size_t)r0 * 512 + cg) =
                    pk(gelu_f(acc[nt][0] + b.x), gelu_f(acc[nt][1] + b.y));
                *(uint32_t*)(g_fb + (size_t)r1 * 512 + cg) =
                    pk(gelu_f(acc[nt][2] + b.x), gelu_f(acc[nt][3] + b.y));
            }
        }
    }
}

// ================= kF2 (tensor): outV = mask * LN2(v1 + g_fb @ Wout + bout) ==========
#define SF2 (512 * 272 + 1536)
__global__ void __launch_bounds__(128, 1)
kF2(const float* __restrict__ Wout, const float* __restrict__ bout,
    const float* __restrict__ g2, const float* __restrict__ bb2,
    const float* __restrict__ maskV, float* __restrict__ outV) {
    extern __shared__ char sm[];
    __nv_bfloat16* Ws = (__nv_bfloat16*)sm;
    float* bs = (float*)(sm + 512 * 272);
    int tid = threadIdx.x, lane = tid & 31, warp = tid >> 5;
    int gid = lane >> 2, tg = lane & 3;
    load_w(Wout, Ws, 512, tid, 128);
    if (tid < 128) { bs[tid] = bout[tid]; bs[128 + tid] = g2[tid]; bs[256 + tid] = bb2[tid]; }
    __syncthreads();
    float* bo = bs; float* g2s = bs + 128; float* b2s = bs + 256;
    uint32_t loff = (uint32_t)(((lane & 15) * LDW + ((lane >> 4) * 8)) * 2);
    uint32_t wAddr = su32(Ws) + loff;

    for (int wt = blockIdx.x * 4 + warp; wt < NTILES; wt += gridDim.x * 4) {
        int r0 = wt * 16 + gid, r1 = r0 + 8;
        const __nv_bfloat16* f0 = g_fb + (size_t)r0 * 512;
        const __nv_bfloat16* f1 = g_fb + (size_t)r1 * 512;
        float acc[16][4];
        zero16(acc);
        #pragma unroll 4
        for (int kt = 0; kt < 32; ++kt) {
            uint32_t a[4];
            int c = kt * 16 + 2 * tg;
            a[0] = *(const uint32_t*)(f0 + c);
            a[1] = *(const uint32_t*)(f1 + c);
            a[2] = *(const uint32_t*)(f0 + c + 8);
            a[3] = *(const uint32_t*)(f1 + c + 8);
            #pragma unroll
            for (int nb = 0; nb < 8; ++nb) {
                uint32_t b[4];
                asm volatile("ldmatrix.sync.aligned.m8n8.x4.trans.shared.b16 {%0,%1,%2,%3},[%4];"
                             : "=r"(b[0]), "=r"(b[1]), "=r"(b[2]), "=r"(b[3])
                             : "r"(wAddr + kt * 4352 + nb * 32));
                MMA4(acc[2 * nb],     a, b[0], b[1]);
                MMA4(acc[2 * nb + 1], a, b[2], b[3]);
            }
        }
        const float* v0 = g_v1 + (size_t)r0 * 128;
        const float* v1 = g_v1 + (size_t)r1 * 128;
        float sum0 = 0.f, sq0 = 0.f, sum1 = 0.f, sq1 = 0.f;
        #pragma unroll
        for (int nt = 0; nt < 16; ++nt) {
            int c = nt * 8 + 2 * tg;
            float2 b  = *(const float2*)(bo + c);
            float2 h0 = *(const float2*)(v0 + c);
            float2 h1 = *(const float2*)(v1 + c);
            acc[nt][0] += b.x + h0.x; acc[nt][1] += b.y + h0.y;
            acc[nt][2] += b.x + h1.x; acc[nt][3] += b.y + h1.y;
            sum0 += acc[nt][0] + acc[nt][1];
            sq0  += acc[nt][0] * acc[nt][0] + acc[nt][1] * acc[nt][1];
            sum1 += acc[nt][2] + acc[nt][3];
            sq1  += acc[nt][2] * acc[nt][2] + acc[nt][3] * acc[nt][3];
        }
        #pragma unroll
        for (int o = 1; o < 4; o <<= 1) {
            sum0 += __shfl_xor_sync(~0u, sum0, o);
            sq0  += __shfl_xor_sync(~0u, sq0, o);
            sum1 += __shfl_xor_sync(~0u, sum1, o);
            sq1  += __shfl_xor_sync(~0u, sq1, o);
        }
        float mu0 = sum0 * (1.0f / 128.0f);
        float iv0 = rsqrtf(sq0 * (1.0f / 128.0f) - mu0 * mu0 + 1e-5f);
        float mu1 = sum1 * (1.0f / 128.0f);
        float iv1 = rsqrtf(sq1 * (1.0f / 128.0f) - mu1 * mu1 + 1e-5f);
        float mv0 = __ldg(maskV + r0), mv1 = __ldg(maskV + r1);
        #pragma unroll
        for (int nt = 0; nt < 16; ++nt) {
            int c = nt * 8 + 2 * tg;
            float gx = g2s[c], gy = g2s[c + 1], bx = b2s[c], by = b2s[c + 1];
            float2 y0 = { ((acc[nt][0] - mu0) * iv0 * gx + bx) * mv0,
                          ((acc[nt][1] - mu0) * iv0 * gy + by) * mv0 };
            float2 y1 = { ((acc[nt][2] - mu1) * iv1 * gx + bx) * mv1,
                          ((acc[nt][3] - mu1) * iv1 * gy + by) * mv1 };
            *(float2*)(outV + (size_t)r0 * 128 + c) = y0;
            *(float2*)(outV + (size_t)r1 * 128 + c) = y1;
            *(uint32_t*)(g_hvb + (size_t)r0 * 128 + c) = pk(y0.x, y0.y);
            *(uint32_t*)(g_hvb + (size_t)r1 * 128 + c) = pk(y1.x, y1.y);
        }
    }
}

extern "C" void kernel_launch(void* const* d_in, const int* in_sizes, int n_in,
                              void* d_out, int out_size) {
    const float* hV = (const float*)d_in[0];
    const float* hE = (const float*)d_in[1];
    const float* mV = (const float*)d_in[2];
    const int* Eidx = (const int*)d_in[3];
    const float* matt = (const float*)d_in[4];
    const float* W1 = (const float*)d_in[5],  *b1 = (const float*)d_in[6];
    const float* W2 = (const float*)d_in[7],  *b2 = (const float*)d_in[8];
    const float* W3 = (const float*)d_in[9],  *b3 = (const float*)d_in[10];
    const float* W11 = (const float*)d_in[11], *b11 = (const float*)d_in[12];
    const float* W12 = (const float*)d_in[13], *b12 = (const float*)d_in[14];
    const float* W13 = (const float*)d_in[15], *b13 = (const float*)d_in[16];
    const float* Win = (const float*)d_in[17], *bin = (const float*)d_in[18];
    const float* Wout = (const float*)d_in[19], *bout = (const float*)d_in[20];
    const float* g1 = (const float*)d_in[21], *bb1 = (const float*)d_in[22];
    const float* g2 = (const float*)d_in[23], *bb2 = (const float*)d_in[24];
    const float* g3 = (const float*)d_in[25], *bb3 = (const float*)d_in[26];
    float* outV = (float*)d_out;
    float* outE = (float*)d_out + HV_ELEMS;
    float* biasA; cudaGetSymbolAddress((void**)&biasA, g_biasA);
    float* biasC; cudaGetSymbolAddress((void**)&biasC, g_biasC);

    cudaFuncSetAttribute(kFoldT, cudaFuncAttributeMaxDynamicSharedMemorySize, SFOLD);
    cudaFuncSetAttribute(kEdge, cudaFuncAttributeMaxDynamicSharedMemorySize, KE_SMEM);
    cudaFuncSetAttribute(kF1, cudaFuncAttributeMaxDynamicSharedMemorySize, SF1);
    cudaFuncSetAttribute(kF2, cudaFuncAttributeMaxDynamicSharedMemorySize, SF2);

    kFoldT<<<128, 128, SFOLD>>>(hV, W1, b1, biasA, 1);
    kEdge<<<148, 512, 104448 + 1024>>>(0, hE, W1 + 128 * 128, W2, W3, 128, b2, b3,
                                       biasA, matt, nullptr, nullptr, nullptr, nullptr);
    kLN1<<<NODES, 128>>>(hV, g1, bb1);
    kF1<<<128, 128, SF1>>>(Win, bin);
    kF2<<<128, 128, SF2>>>(Wout, bout, g2, bb2, mV, outV);
    kFoldT<<<128, 128, SFOLD>>>(outV, W11, b11, biasC, 0);
    kEdge<<<148, 512, KE_SMEM>>>(1, hE, W11 + 128 * 128, W12, W13, 256, b12, b13,
                                 biasC, nullptr, Eidx, g3, bb3, outE);
}

// round 10
// speedup vs baseline: 2.4384x; 1.0205x over previous
#include <cuda_runtime.h>
#include <cuda_bf16.h>
#include <cstdint>

#define NODES 8192
#define H_ 128
#define K_ 48
#define EDGES (NODES * K_)
#define WTILES (EDGES / 16)
#define NTILES (NODES / 16)
#define HV_ELEMS (NODES * H_)
#define LDW 136

__device__ __align__(16) float         g_v1[NODES * H_];
__device__ __align__(16) __nv_bfloat16 g_fb[NODES * 512];
__device__ __align__(16) __nv_bfloat16 g_hvb[NODES * H_];
__device__ __align__(16) float         g_dh[NODES * H_];
__device__ __align__(16) float         g_biasA[NODES * H_];
__device__ __align__(16) float         g_biasC[NODES * H_];

static __device__ __forceinline__ unsigned su32(const void* p) {
    return (unsigned)__cvta_generic_to_shared(p);
}
static __device__ __forceinline__ float gelu_f(float x) {
    float u = 0.7978845608028654f * (x + 0.044715f * x * x * x), t;
    asm("tanh.approx.f32 %0, %1;" : "=f"(t) : "f"(u));
    return 0.5f * x * (1.0f + t);
}
static __device__ __forceinline__ uint32_t pk(float x, float y) {
    __nv_bfloat162 h = __floats2bfloat162_rn(x, y);
    return *(uint32_t*)&h;
}
static __device__ __forceinline__ void load_w(const float* g, __nv_bfloat16* s,
                                              int rows, int tid, int nthr) {
    int total4 = rows * 32;
    for (int i = tid; i < total4; i += nthr) {
        float4 w = ((const float4*)g)[i];
        int r = (i * 4) >> 7, c = (i * 4) & 127;
        *(__nv_bfloat162*)(s + r * LDW + c)     = __floats2bfloat162_rn(w.x, w.y);
        *(__nv_bfloat162*)(s + r * LDW + c + 2) = __floats2bfloat162_rn(w.z, w.w);
    }
}

#define MMA4(ac, a, b0, b1) \
    asm volatile("mma.sync.aligned.m16n8k16.row.col.f32.bf16.bf16.f32 " \
                 "{%0,%1,%2,%3},{%4,%5,%6,%7},{%8,%9},{%0,%1,%2,%3};" \
                 : "+f"((ac)[0]), "+f"((ac)[1]), "+f"((ac)[2]), "+f"((ac)[3]) \
                 : "r"((a)[0]), "r"((a)[1]), "r"((a)[2]), "r"((a)[3]), \
                   "r"(b0), "r"(b1))

static __device__ __forceinline__ void zero16(float acc[16][4]) {
    #pragma unroll
    for (int i = 0; i < 16; ++i)
        #pragma unroll
        for (int j = 0; j < 4; ++j) acc[i][j] = 0.0f;
}

template <int NKT>
static __device__ __forceinline__ void gemm_reg(const uint32_t* af, uint32_t wAddr,
                                                float acc[16][4]) {
    #pragma unroll
    for (int kt = 0; kt < NKT; ++kt) {
        #pragma unroll
        for (int nb = 0; nb < 8; ++nb) {
            uint32_t b[4];
            asm volatile("ldmatrix.sync.aligned.m8n8.x4.trans.shared.b16 {%0,%1,%2,%3},[%4];"
                         : "=r"(b[0]), "=r"(b[1]), "=r"(b[2]), "=r"(b[3])
                         : "r"(wAddr + kt * 4352 + nb * 32));
            MMA4(acc[2 * nb],     af + 4 * kt, b[0], b[1]);
            MMA4(acc[2 * nb + 1], af + 4 * kt, b[2], b[3]);
        }
    }
}

static __device__ __forceinline__ void load_af_f32(const float* r0, const float* r1,
                                                   int tg, uint32_t af[32]) {
    #pragma unroll
    for (int kt = 0; kt < 8; ++kt) {
        int c = kt * 16 + 2 * tg;
        float2 v0 = *(const float2*)(r0 + c);
        float2 v1 = *(const float2*)(r1 + c);
        float2 v2 = *(const float2*)(r0 + c + 8);
        float2 v3 = *(const float2*)(r1 + c + 8);
        af[4 * kt]     = pk(v0.x, v0.y);
        af[4 * kt + 1] = pk(v1.x, v1.y);
        af[4 * kt + 2] = pk(v2.x, v2.y);
        af[4 * kt + 3] = pk(v3.x, v3.y);
    }
}
static __device__ __forceinline__ void load_af_bf16(const __nv_bfloat16* r0,
                                                    const __nv_bfloat16* r1,
                                                    int tg, uint32_t af[32]) {
    #pragma unroll
    for (int kt = 0; kt < 8; ++kt) {
        int c = kt * 16 + 2 * tg;
        af[4 * kt]     = *(const uint32_t*)(r0 + c);
        af[4 * kt + 1] = *(const uint32_t*)(r1 + c);
        af[4 * kt + 2] = *(const uint32_t*)(r0 + c + 8);
        af[4 * kt + 3] = *(const uint32_t*)(r1 + c + 8);
    }
}
static __device__ __forceinline__ void pack_gelu(const float acc[16][4],
                                                 const float* bias, int tg,
                                                 uint32_t af[32]) {
    #pragma unroll
    for (int kt = 0; kt < 8; ++kt) {
        int n0 = 2 * kt, n1 = 2 * kt + 1;
        float2 bA = *(const float2*)(bias + n0 * 8 + 2 * tg);
        float2 bB = *(const float2*)(bias + n1 * 8 + 2 * tg);
        af[4 * kt]     = pk(gelu_f(acc[n0][0] + bA.x), gelu_f(acc[n0][1] + bA.y));
        af[4 * kt + 1] = pk(gelu_f(acc[n0][2] + bA.x), gelu_f(acc[n0][3] + bA.y));
        af[4 * kt + 2] = pk(gelu_f(acc[n1][0] + bB.x), gelu_f(acc[n1][1] + bB.y));
        af[4 * kt + 3] = pk(gelu_f(acc[n1][2] + bB.x), gelu_f(acc[n1][3] + bB.y));
    }
}

// ================= kFoldT: biasA = b1 + hV @ W1[0:128]; zero g_dh =================
#define SFOLD (34816 + 512)
__global__ void __launch_bounds__(256, 1)
kFoldT(const float* __restrict__ x, const float* __restrict__ W,
       const float* __restrict__ b, float* __restrict__ out, int zdh) {
    extern __shared__ char sm[];
    __nv_bfloat16* Ws = (__nv_bfloat16*)sm;
    float* bsm = (float*)(sm + 34816);
    int tid = threadIdx.x, lane = tid & 31, warp = tid >> 5;
    int gid = lane >> 2, tg = lane & 3;
    load_w(W, Ws, 128, tid, 256);
    if (tid < 128) bsm[tid] = b[tid];
    __syncthreads();
    uint32_t loff = (uint32_t)(((lane & 15) * LDW + ((lane >> 4) * 8)) * 2);
    uint32_t wAddr = su32(Ws) + loff;
    for (int wt = blockIdx.x * 8 + warp; wt < NTILES; wt += gridDim.x * 8) {
        int r0 = wt * 16 + gid, r1 = r0 + 8;
        uint32_t af[32];
        float acc[16][4];
        load_af_f32(x + (size_t)r0 * 128, x + (size_t)r1 * 128, tg, af);
        zero16(acc);
        gemm_reg<8>(af, wAddr, acc);
        #pragma unroll
        for (int nt = 0; nt < 16; ++nt) {
            int c = nt * 8 + 2 * tg;
            float2 bb = *(const float2*)(bsm + c);
            *(float2*)(out + (size_t)r0 * 128 + c) = make_float2(acc[nt][0] + bb.x, acc[nt][1] + bb.y);
            *(float2*)(out + (size_t)r1 * 128 + c) = make_float2(acc[nt][2] + bb.x, acc[nt][3] + bb.y);
            if (zdh) {
                *(float2*)(g_dh + (size_t)r0 * 128 + c) = make_float2(0.f, 0.f);
                *(float2*)(g_dh + (size_t)r1 * 128 + c) = make_float2(0.f, 0.f);
            }
        }
    }
}

// ================= kEdge (unchanged from R9: register-resident MLP + prefetch) ========
#define KE_SMEM (69632 + 34816 + 34816 + 1024)
__global__ void __launch_bounds__(512, 1)
kEdge(int mode, const float* __restrict__ hE,
      const float* __restrict__ Wl1, const float* __restrict__ Wl2,
      const float* __restrict__ Wl3, int K1,
      const float* __restrict__ b2, const float* __restrict__ b3,
      const float* __restrict__ bias1, const float* __restrict__ matt,
      const int* __restrict__ Eidx, const float* __restrict__ g3,
      const float* __restrict__ bb3, float* __restrict__ outE) {
    extern __shared__ char sm[];
    __nv_bfloat16* W1s = (__nv_bfloat16*)sm;
    float* bs = (float*)(sm + K1 * 272 + 69632);
    int tid = threadIdx.x, lane = tid & 31, warp = tid >> 5;
    int gid = lane >> 2, tg = lane & 3;

    load_w(Wl1, W1s, K1, tid, 512);
    load_w(Wl2, (__nv_bfloat16*)(sm + K1 * 272), 128, tid, 512);
    load_w(Wl3, (__nv_bfloat16*)(sm + K1 * 272 + 34816), 128, tid, 512);
    if (tid < 128) { bs[tid] = b2[tid]; bs[128 + tid] = b3[tid]; }
    __syncthreads();
    float* b2s = bs; float* b3s = bs + 128;

    uint32_t loff = (uint32_t)(((lane & 15) * LDW + ((lane >> 4) * 8)) * 2);
    uint32_t w1Addr = su32(sm) + loff;
    uint32_t w2Addr = w1Addr + K1 * 272;
    uint32_t w3Addr = w2Addr + 34816;

    const int stride = gridDim.x * 16;
    int wt = blockIdx.x * 16 + warp;
    uint32_t af[32];
    float acc[16][4];
    if (wt < WTILES) {
        int r0 = wt * 16 + gid;
        load_af_f32(hE + (size_t)r0 * 128, hE + (size_t)(r0 + 8) * 128, tg, af);
    }
    while (wt < WTILES) {
        int rowbase = wt * 16;
        int r0 = rowbase + gid, r1 = r0 + 8;
        int node = rowbase / 48;
        int nb0 = 0, nb1 = 0;
        if (mode) {
            int bbase = (rowbase / 98304) * 2048;
            nb0 = bbase + Eidx[r0];
            nb1 = bbase + Eidx[r1];
        }
        zero16(acc);
        gemm_reg<8>(af, w1Addr, acc);
        if (mode) {
            load_af_bf16(g_hvb + (size_t)nb0 * 128, g_hvb + (size_t)nb1 * 128, tg, af);
            gemm_reg<8>(af, w1Addr + 128 * 272, acc);
        }
        pack_gelu(acc, bias1 + (size_t)node * 128, tg, af);
        zero16(acc);
        gemm_reg<8>(af, w2Addr, acc);
        pack_gelu(acc, b2s, tg, af);
        zero16(acc);
        gemm_reg<8>(af, w3Addr, acc);

        int wtn = wt + stride;
        if (wtn < WTILES) {
            int rn = wtn * 16 + gid;
            load_af_f32(hE + (size_t)rn * 128, hE + (size_t)(rn + 8) * 128, tg, af);
        }

        if (mode == 0) {
            float m0 = __ldg(matt + r0), m1 = __ldg(matt + r1);
            #pragma unroll
            for (int nt = 0; nt < 16; ++nt) {
                float2 b = *(const float2*)(b3s + nt * 8 + 2 * tg);
                acc[nt][0] = (acc[nt][0] + b.x) * m0 + (acc[nt][2] + b.x) * m1;
                acc[nt][1] = (acc[nt][1] + b.y) * m0 + (acc[nt][3] + b.y) * m1;
            }
            #pragma unroll
            for (int o = 4; o < 32; o <<= 1)
                #pragma unroll
                for (int nt = 0; nt < 16; ++nt) {
                    acc[nt][0] += __shfl_xor_sync(~0u, acc[nt][0], o);
                    acc[nt][1] += __shfl_xor_sync(~0u, acc[nt][1], o);
                }
            if (lane < 4) {
                float* dst = g_dh + (size_t)node * 128;
                #pragma unroll
                for (int nt = 0; nt < 16; ++nt) {
                    atomicAdd(dst + nt * 8 + 2 * lane,     acc[nt][0]);
                    atomicAdd(dst + nt * 8 + 2 * lane + 1, acc[nt][1]);
                }
            }
        } else {
            const float* e0 = hE + (size_t)r0 * 128;
            const float* e1 = hE + (size_t)r1 * 128;
            float sum0 = 0.f, sq0 = 0.f, sum1 = 0.f, sq1 = 0.f;
            #pragma unroll
            for (int nt = 0; nt < 16; ++nt) {
                int c = nt * 8 + 2 * tg;
                float2 b  = *(const float2*)(b3s + c);
                float2 h0 = *(const float2*)(e0 + c);
                float2 h1 = *(const float2*)(e1 + c);
                acc[nt][0] += b.x + h0.x; acc[nt][1] += b.y + h0.y;
                acc[nt][2] += b.x + h1.x; acc[nt][3] += b.y + h1.y;
                sum0 += acc[nt][0] + acc[nt][1];
                sq0  += acc[nt][0] * acc[nt][0] + acc[nt][1] * acc[nt][1];
                sum1 += acc[nt][2] + acc[nt][3];
                sq1  += acc[nt][2] * acc[nt][2] + acc[nt][3] * acc[nt][3];
            }
            #pragma unroll
            for (int o = 1; o < 4; o <<= 1) {
                sum0 += __shfl_xor_sync(~0u, sum0, o);
                sq0  += __shfl_xor_sync(~0u, sq0, o);
                sum1 += __shfl_xor_sync(~0u, sum1, o);
                sq1  += __shfl_xor_sync(~0u, sq1, o);
            }
            float mu0 = sum0 * (1.0f / 128.0f);
            float iv0 = rsqrtf(sq0 * (1.0f / 128.0f) - mu0 * mu0 + 1e-5f);
            float mu1 = sum1 * (1.0f / 128.0f);
            float iv1 = rsqrtf(sq1 * (1.0f / 128.0f) - mu1 * mu1 + 1e-5f);
            float* o0 = outE + (size_t)r0 * 128;
            float* o1 = outE + (size_t)r1 * 128;
            #pragma unroll
            for (int nt = 0; nt < 16; ++nt) {
                int c = nt * 8 + 2 * tg;
                float gx = __ldg(g3 + c), gy = __ldg(g3 + c + 1);
                float bx = __ldg(bb3 + c), by = __ldg(bb3 + c + 1);
                *(float2*)(o0 + c) = make_float2((acc[nt][0] - mu0) * iv0 * gx + bx,
                                                 (acc[nt][1] - mu0) * iv0 * gy + by);
                *(float2*)(o1 + c) = make_float2((acc[nt][2] - mu1) * iv1 * gx + bx,
                                                 (acc[nt][3] - mu1) * iv1 * gy + by);
            }
        }
        wt = wtn;
    }
}

// ============ kF1 (fused LN1): v1 = LN1(hV + dh/30); g_fb = gelu(v1 @ Win + bin) =====
#define SF1 (4 * 34816 + 2048 + 1024)
__global__ void __launch_bounds__(256, 1)
kF1(const float* __restrict__ hV, const float* __restrict__ Win,
    const float* __restrict__ bin, const float* __restrict__ g1,
    const float* __restrict__ bb1) {
    extern __shared__ char sm[];
    float* bin_s = (float*)(sm + 4 * 34816);
    float* g1s = bin_s + 512;
    float* b1s = g1s + 128;
    int tid = threadIdx.x, lane = tid & 31, warp = tid >> 5;
    int gid = lane >> 2, tg = lane & 3;
    for (int i = tid; i < 16384; i += 256) {
        float4 w = ((const float4*)Win)[i];
        int k = i >> 7, n = (i * 4) & 511;
        __nv_bfloat16* dst = (__nv_bfloat16*)(sm + (n >> 7) * 34816);
        int cc = n & 127;
        *(__nv_bfloat162*)(dst + k * LDW + cc)     = __floats2bfloat162_rn(w.x, w.y);
        *(__nv_bfloat162*)(dst + k * LDW + cc + 2) = __floats2bfloat162_rn(w.z, w.w);
    }
    for (int i = tid; i < 512; i += 256) bin_s[i] = bin[i];
    if (tid < 128) { g1s[tid] = g1[tid]; b1s[tid] = bb1[tid]; }
    __syncthreads();
    uint32_t loff = (uint32_t)(((lane & 15) * LDW + ((lane >> 4) * 8)) * 2);

    for (int wt = blockIdx.x * 8 + warp; wt < NTILES; wt += gridDim.x * 8) {
        int r0 = wt * 16 + gid, r1 = r0 + 8;
        const float* hv0 = hV + (size_t)r0 * 128;
        const float* hv1 = hV + (size_t)r1 * 128;
        const float* dh0 = g_dh + (size_t)r0 * 128;
        const float* dh1 = g_dh + (size_t)r1 * 128;
        float x0[32], x1[32];
        float sum0 = 0.f, sq0 = 0.f, sum1 = 0.f, sq1 = 0.f;
        #pragma unroll
        for (int j = 0; j < 16; ++j) {
            int c = (j >> 1) * 16 + (j & 1) * 8 + 2 * tg;
            float2 a0 = *(const float2*)(hv0 + c);
            float2 d0 = *(const float2*)(dh0 + c);
            float2 a1 = *(const float2*)(hv1 + c);
            float2 d1 = *(const float2*)(dh1 + c);
            x0[2 * j]     = a0.x + d0.x * (1.0f / 30.0f);
            x0[2 * j + 1] = a0.y + d0.y * (1.0f / 30.0f);
            x1[2 * j]     = a1.x + d1.x * (1.0f / 30.0f);
            x1[2 * j + 1] = a1.y + d1.y * (1.0f / 30.0f);
            sum0 += x0[2 * j] + x0[2 * j + 1];
            sq0  += x0[2 * j] * x0[2 * j] + x0[2 * j + 1] * x0[2 * j + 1];
            sum1 += x1[2 * j] + x1[2 * j + 1];
            sq1  += x1[2 * j] * x1[2 * j] + x1[2 * j + 1] * x1[2 * j + 1];
        }
        #pragma unroll
        for (int o = 1; o < 4; o <<= 1) {
            sum0 += __shfl_xor_sync(~0u, sum0, o);
            sq0  += __shfl_xor_sync(~0u, sq0, o);
            sum1 += __shfl_xor_sync(~0u, sum1, o);
            sq1  += __shfl_xor_sync(~0u, sq1, o);
        }
        float mu0 = sum0 * (1.0f / 128.0f);
        float iv0 = rsqrtf(sq0 * (1.0f / 128.0f) - mu0 * mu0 + 1e-5f);
        float mu1 = sum1 * (1.0f / 128.0f);
        float iv1 = rsqrtf(sq1 * (1.0f / 128.0f) - mu1 * mu1 + 1e-5f);
        uint32_t af[32];
        #pragma unroll
        for (int j = 0; j < 16; ++j) {
            int c = (j >> 1) * 16 + (j & 1) * 8 + 2 * tg;
            float y0a = (x0[2 * j] - mu0) * iv0 * g1s[c] + b1s[c];
            float y0b = (x0[2 * j + 1] - mu0) * iv0 * g1s[c + 1] + b1s[c + 1];
            float y1a = (x1[2 * j] - mu1) * iv1 * g1s[c] + b1s[c];
            float y1b = (x1[2 * j + 1] - mu1) * iv1 * g1s[c + 1] + b1s[c + 1];
            *(float2*)(g_v1 + (size_t)r0 * 128 + c) = make_float2(y0a, y0b);
            *(float2*)(g_v1 + (size_t)r1 * 128 + c) = make_float2(y1a, y1b);
            int kt = j >> 1, half = j & 1;
            af[4 * kt + 2 * half]     = pk(y0a, y0b);
            af[4 * kt + 2 * half + 1] = pk(y1a, y1b);
        }
        float acc[16][4];
        #pragma unroll
        for (int ng = 0; ng < 4; ++ng) {
            zero16(acc);
            gemm_reg<8>(af, su32(sm + ng * 34816) + loff, acc);
            #pragma unroll
            for (int nt = 0; nt < 16; ++nt) {
                int cg = ng * 128 + nt * 8 + 2 * tg;
                float2 b = *(const float2*)(bin_s + cg);
                *(uint32_t*)(g_fb + (size_t)r0 * 512 + cg) =
                    pk(gelu_f(acc[nt][0] + b.x), gelu_f(acc[nt][1] + b.y));
                *(uint32_t*)(g_fb + (size_t)r1 * 512 + cg) =
                    pk(gelu_f(acc[nt][2] + b.x), gelu_f(acc[nt][3] + b.y));
            }
        }
    }
}

// ==== kF2 (fused fold): outV = mask*LN2(v1 + fb@Wout + bout); biasC = b11 + outV@W11 ==
#define SF2 (139264 + 34816 + 2048)
__global__ void __launch_bounds__(256, 1)
kF2(const float* __restrict__ Wout, const float* __restrict__ bout,
    const float* __restrict__ g2, const float* __restrict__ bb2,
    const float* __restrict__ maskV, float* __restrict__ outV,
    const float* __restrict__ W11, const float* __restrict__ b11,
    float* __restrict__ biasC) {
    extern __shared__ char sm[];
    __nv_bfloat16* Ws = (__nv_bfloat16*)sm;
    __nv_bfloat16* W11s = (__nv_bfloat16*)(sm + 139264);
    float* bs = (float*)(sm + 139264 + 34816);
    int tid = threadIdx.x, lane = tid & 31, warp = tid >> 5;
    int gid = lane >> 2, tg = lane & 3;
    load_w(Wout, Ws, 512, tid, 256);
    load_w(W11, W11s, 128, tid, 256);
    if (tid < 128) { bs[tid] = bout[tid]; bs[128 + tid] = g2[tid];
                     bs[256 + tid] = bb2[tid]; bs[384 + tid] = b11[tid]; }
    __syncthreads();
    float* bo = bs; float* g2s = bs + 128; float* b2s = bs + 256; float* b11s = bs + 384;
    uint32_t loff = (uint32_t)(((lane & 15) * LDW + ((lane >> 4) * 8)) * 2);
    uint32_t wAddr = su32(Ws) + loff;
    uint32_t w11Addr = su32(W11s) + loff;

    for (int wt = blockIdx.x * 8 + warp; wt < NTILES; wt += gridDim.x * 8) {
        int r0 = wt * 16 + gid, r1 = r0 + 8;
        const __nv_bfloat16* f0 = g_fb + (size_t)r0 * 512;
        const __nv_bfloat16* f1 = g_fb + (size_t)r1 * 512;
        float acc[16][4];
        zero16(acc);
        #pragma unroll 4
        for (int kt = 0; kt < 32; ++kt) {
            uint32_t a[4];
            int c = kt * 16 + 2 * tg;
            a[0] = *(const uint32_t*)(f0 + c);
            a[1] = *(const uint32_t*)(f1 + c);
            a[2] = *(const uint32_t*)(f0 + c + 8);
            a[3] = *(const uint32_t*)(f1 + c + 8);
            #pragma unroll
            for (int nb = 0; nb < 8; ++nb) {
                uint32_t b[4];
                asm volatile("ldmatrix.sync.aligned.m8n8.x4.trans.shared.b16 {%0,%1,%2,%3},[%4];"
                             : "=r"(b[0]), "=r"(b[1]), "=r"(b[2]), "=r"(b[3])
                             : "r"(wAddr + kt * 4352 + nb * 32));
                MMA4(acc[2 * nb],     a, b[0], b[1]);
                MMA4(acc[2 * nb + 1], a, b[2], b[3]);
            }
        }
        const float* v0 = g_v1 + (size_t)r0 * 128;
        const float* v1 = g_v1 + (size_t)r1 * 128;
        float sum0 = 0.f, sq0 = 0.f, sum1 = 0.f, sq1 = 0.f;
        #pragma unroll
        for (int nt = 0; nt < 16; ++nt) {
            int c = nt * 8 + 2 * tg;
            float2 b  = *(const float2*)(bo + c);
            float2 h0 = *(const float2*)(v0 + c);
            float2 h1 = *(const float2*)(v1 + c);
            acc[nt][0] += b.x + h0.x; acc[nt][1] += b.y + h0.y;
            acc[nt][2] += b.x + h1.x; acc[nt][3] += b.y + h1.y;
            sum0 += acc[nt][0] + acc[nt][1];
            sq0  += acc[nt][0] * acc[nt][0] + acc[nt][1] * acc[nt][1];
            sum1 += acc[nt][2] + acc[nt][3];
            sq1  += acc[nt][2] * acc[nt][2] + acc[nt][3] * acc[nt][3];
        }
        #pragma unroll
        for (int o = 1; o < 4; o <<= 1) {
            sum0 += __shfl_xor_sync(~0u, sum0, o);
            sq0  += __shfl_xor_sync(~0u, sq0, o);
            sum1 += __shfl_xor_sync(~0u, sum1, o);
            sq1  += __shfl_xor_sync(~0u, sq1, o);
        }
        float mu0 = sum0 * (1.0f / 128.0f);
        float iv0 = rsqrtf(sq0 * (1.0f / 128.0f) - mu0 * mu0 + 1e-5f);
        float mu1 = sum1 * (1.0f / 128.0f);
        float iv1 = rsqrtf(sq1 * (1.0f / 128.0f) - mu1 * mu1 + 1e-5f);
        float mv0 = __ldg(maskV + r0), mv1 = __ldg(maskV + r1);
        uint32_t af[32];
        #pragma unroll
        for (int nt = 0; nt < 16; ++nt) {
            int c = nt * 8 + 2 * tg;
            float gx = g2s[c], gy = g2s[c + 1], bx = b2s[c], by = b2s[c + 1];
            float2 y0 = { ((acc[nt][0] - mu0) * iv0 * gx + bx) * mv0,
                          ((acc[nt][1] - mu0) * iv0 * gy + by) * mv0 };
            float2 y1 = { ((acc[nt][2] - mu1) * iv1 * gx + bx) * mv1,
                          ((acc[nt][3] - mu1) * iv1 * gy + by) * mv1 };
            *(float2*)(outV + (size_t)r0 * 128 + c) = y0;
            *(float2*)(outV + (size_t)r1 * 128 + c) = y1;
            uint32_t p0 = pk(y0.x, y0.y), p1 = pk(y1.x, y1.y);
            *(uint32_t*)(g_hvb + (size_t)r0 * 128 + c) = p0;
            *(uint32_t*)(g_hvb + (size_t)r1 * 128 + c) = p1;
            int kt = nt >> 1, half = nt & 1;
            af[4 * kt + 2 * half]     = p0;
            af[4 * kt + 2 * half + 1] = p1;
        }
        // fused fold: biasC = b11 + y @ W11[0:128]
        zero16(acc);
        gemm_reg<8>(af, w11Addr, acc);
        #pragma unroll
        for (int nt = 0; nt < 16; ++nt) {
            int c = nt * 8 + 2 * tg;
            float2 bb = *(const float2*)(b11s + c);
            *(float2*)(biasC + (size_t)r0 * 128 + c) = make_float2(acc[nt][0] + bb.x, acc[nt][1] + bb.y);
            *(float2*)(biasC + (size_t)r1 * 128 + c) = make_float2(acc[nt][2] + bb.x, acc[nt][3] + bb.y);
        }
    }
}

extern "C" void kernel_launch(void* const* d_in, const int* in_sizes, int n_in,
                              void* d_out, int out_size) {
    const float* hV = (const float*)d_in[0];
    const float* hE = (const float*)d_in[1];
    const float* mV = (const float*)d_in[2];
    const int* Eidx = (const int*)d_in[3];
    const float* matt = (const float*)d_in[4];
    const float* W1 = (const float*)d_in[5],  *b1 = (const float*)d_in[6];
    const float* W2 = (const float*)d_in[7],  *b2 = (const float*)d_in[8];
    const float* W3 = (const float*)d_in[9],  *b3 = (const float*)d_in[10];
    const float* W11 = (const float*)d_in[11], *b11 = (const float*)d_in[12];
    const float* W12 = (const float*)d_in[13], *b12 = (const float*)d_in[14];
    const float* W13 = (const float*)d_in[15], *b13 = (const float*)d_in[16];
    const float* Win = (const float*)d_in[17], *bin = (const float*)d_in[18];
    const float* Wout = (const float*)d_in[19], *bout = (const float*)d_in[20];
    const float* g1 = (const float*)d_in[21], *bb1 = (const float*)d_in[22];
    const float* g2 = (const float*)d_in[23], *bb2 = (const float*)d_in[24];
    const float* g3 = (const float*)d_in[25], *bb3 = (const float*)d_in[26];
    float* outV = (float*)d_out;
    float* outE = (float*)d_out + HV_ELEMS;
    float* biasA; cudaGetSymbolAddress((void**)&biasA, g_biasA);
    float* biasC; cudaGetSymbolAddress((void**)&biasC, g_biasC);

    cudaFuncSetAttribute(kFoldT, cudaFuncAttributeMaxDynamicSharedMemorySize, SFOLD);
    cudaFuncSetAttribute(kEdge, cudaFuncAttributeMaxDynamicSharedMemorySize, KE_SMEM);
    cudaFuncSetAttribute(kF1, cudaFuncAttributeMaxDynamicSharedMemorySize, SF1);
    cudaFuncSetAttribute(kF2, cudaFuncAttributeMaxDynamicSharedMemorySize, SF2);

    kFoldT<<<64, 256, SFOLD>>>(hV, W1, b1, biasA, 1);
    kEdge<<<148, 512, 104448 + 1024>>>(0, hE, W1 + 128 * 128, W2, W3, 128, b2, b3,
                                       biasA, matt, nullptr, nullptr, nullptr, nullptr);
    kF1<<<64, 256, SF1>>>(hV, Win, bin, g1, bb1);
    kF2<<<64, 256, SF2>>>(Wout, bout, g2, bb2, mV, outV, W11, b11, biasC);
    kEdge<<<148, 512, KE_SMEM>>>(1, hE, W11 + 128 * 128, W12, W13, 256, b12, b13,
                                 biasC, nullptr, Eidx, g3, bb3, outE);
}